// round 13
// baseline (speedup 1.0000x reference)
#include <cuda_runtime.h>
#include <cuda_fp16.h>
#include <math.h>
#include <stdint.h>

#define N_NODES 4096
#define E_TYPES 5
#define W_IN 512
#define W_OUT 128
#define NUM_CLASS 16
#define M_TGT 1024
#define NUM_LAYERS 64
#define H0 (W_IN + E_TYPES * W_OUT)   // 1152
#define NNZ_CAP 2097152
#define CAPE 262144
#define ATT_G 128
#define NWIN 16
#define WINC 256

// ---------------- static scratch ----------------
__device__ __half g_Xh[N_NODES * W_IN];
__device__ __half g_Wgh[W_IN * W_IN];
__device__ __half g_weighth[W_IN * W_OUT];
__device__ __half g_W0h[H0 * W_OUT];
__device__ __half g_Xgh[N_NODES * W_IN];
__device__ float g_Xw[N_NODES * W_OUT];
__device__ float g_lgcn[E_TYPES * N_NODES * W_OUT];
__device__ float g_attpart[E_TYPES * ATT_G * W_OUT];
__device__ float g_beta[E_TYPES];
__device__ __half g_Xcath[N_NODES * H0];
__device__ float g_x0[N_NODES * W_OUT];
__device__ float g_xlast[N_NODES * W_OUT];
__device__ __half g_xh0[N_NODES * W_OUT];
__device__ __half g_xhA[N_NODES * W_OUT];
__device__ __half g_xhB[N_NODES * W_OUT];
__device__ float g_wprime[(size_t)NUM_LAYERS * W_OUT * W_OUT];  // (1-bl)I + bl*Wl fp32
__device__ float g_part[(size_t)NWIN * N_NODES * W_OUT];        // 33.5MB
__device__ int   g_wstart[N_NODES * (NWIN + 1)];
__device__ float g_Z1[N_NODES * W_OUT];
__device__ float g_Z2[N_NODES * W_OUT];
__device__ float g_y[M_TGT * NUM_CLASS];
__device__ int   g_cnt[N_NODES];
__device__ int   g_rowptr[N_NODES + 1];
__device__ float g_dis[N_NODES];
__device__ int   g_col[NNZ_CAP];
__device__ float g_val[NNZ_CAP];
__device__ int   g_zinit[3 * E_TYPES * N_NODES];
__device__ int   g_cptr[E_TYPES * (N_NODES + 1)];
__device__ int   g_csrc[E_TYPES * CAPE];
__device__ float g_cval[E_TYPES * CAPE];

// ---------------- helpers ----------------
__device__ __forceinline__ float h2_as_f(__half2 h) {
    return __uint_as_float(*(unsigned*)&h);
}
__device__ __forceinline__ uint32_t smem_u32(const void* p) {
    uint32_t a;
    asm("{ .reg .u64 t; cvta.to.shared.u64 t, %1; cvt.u32.u64 %0, t; }" : "=r"(a) : "l"(p));
    return a;
}
__device__ __forceinline__ void cpa16(uint32_t dst, const void* src) {
    asm volatile("cp.async.cg.shared.global [%0], [%1], 16;" :: "r"(dst), "l"(src));
}
__device__ __forceinline__ void ldmx4(uint32_t& r0, uint32_t& r1, uint32_t& r2,
                                      uint32_t& r3, uint32_t addr) {
    asm volatile("ldmatrix.sync.aligned.m8n8.x4.shared.b16 {%0,%1,%2,%3}, [%4];"
                 : "=r"(r0), "=r"(r1), "=r"(r2), "=r"(r3) : "r"(addr));
}
__device__ __forceinline__ void ldmx4t(uint32_t& r0, uint32_t& r1, uint32_t& r2,
                                       uint32_t& r3, uint32_t addr) {
    asm volatile("ldmatrix.sync.aligned.m8n8.x4.trans.shared.b16 {%0,%1,%2,%3}, [%4];"
                 : "=r"(r0), "=r"(r1), "=r"(r2), "=r"(r3) : "r"(addr));
}
__device__ __forceinline__ void mma16816(float* c, uint32_t a0, uint32_t a1, uint32_t a2,
                                         uint32_t a3, uint32_t b0, uint32_t b1) {
    asm volatile(
        "mma.sync.aligned.m16n8k16.row.col.f32.f16.f16.f32 "
        "{%0,%1,%2,%3}, {%4,%5,%6,%7}, {%8,%9}, {%0,%1,%2,%3};"
        : "+f"(c[0]), "+f"(c[1]), "+f"(c[2]), "+f"(c[3])
        : "r"(a0), "r"(a1), "r"(a2), "r"(a3), "r"(b0), "r"(b1));
}

// ---------------- generic fp16 HMMA GEMM with epilogue ----------------
__global__ __launch_bounds__(256, 1) void hgemm(
    const __half* __restrict__ A, const __half* __restrict__ B,
    int M, int N, int K, const float* __restrict__ bias, int act,
    float* __restrict__ Cf, __half* __restrict__ Ch) {
    __shared__ __half As[2][128 * 40];
    __shared__ __half Bs[2][32 * 136];
    int t = threadIdx.x, w = t >> 5, lane = t & 31;
    int m0 = blockIdx.x * 128, n0 = blockIdx.y * 128;
    const __half* Ag = A + (size_t)m0 * K;
    const __half* Bg = B + n0;
    uint32_t asb[2] = {smem_u32(As[0]), smem_u32(As[1])};
    uint32_t bsb[2] = {smem_u32(Bs[0]), smem_u32(Bs[1])};

    auto prefetch = [&](int i, int buf) {
#pragma unroll
        for (int j = 0; j < 2; j++) {
            int cid = t + 256 * j;
            int r = cid >> 2, co = (cid & 3) * 8;
            cpa16(asb[buf] + (r * 40 + co) * 2, Ag + (size_t)r * K + i * 32 + co);
            int rb = cid >> 4, cb = (cid & 15) * 8;
            cpa16(bsb[buf] + (rb * 136 + cb) * 2, Bg + (size_t)(i * 32 + rb) * N + cb);
        }
        asm volatile("cp.async.commit_group;" ::: "memory");
    };
    prefetch(0, 0);
    prefetch(1, 1);

    int wm = w >> 2, wn = w & 3;
    float c[4][4][4];
#pragma unroll
    for (int mi = 0; mi < 4; mi++)
#pragma unroll
        for (int nj = 0; nj < 4; nj++)
#pragma unroll
            for (int q = 0; q < 4; q++) c[mi][nj][q] = 0.f;

    int niter = K / 32;
    for (int i = 0; i < niter; i++) {
        asm volatile("cp.async.wait_group 1;" ::: "memory");
        __syncthreads();
        int buf = i & 1;
        uint32_t ab = asb[buf], bb = bsb[buf];
#pragma unroll
        for (int kk = 0; kk < 2; kk++) {
            uint32_t a[4][4];
#pragma unroll
            for (int mi = 0; mi < 4; mi++) {
                int row = wm * 64 + mi * 16 + (lane & 15);
                int col = kk * 16 + (lane >> 4) * 8;
                ldmx4(a[mi][0], a[mi][1], a[mi][2], a[mi][3], ab + (row * 40 + col) * 2);
            }
            uint32_t b[2][4];
#pragma unroll
            for (int ng = 0; ng < 2; ng++) {
                int row = kk * 16 + (lane & 15);
                int col = wn * 32 + ng * 16 + (lane >> 4) * 8;
                ldmx4t(b[ng][0], b[ng][1], b[ng][2], b[ng][3], bb + (row * 136 + col) * 2);
            }
#pragma unroll
            for (int mi = 0; mi < 4; mi++)
#pragma unroll
                for (int nj = 0; nj < 4; nj++)
                    mma16816(c[mi][nj], a[mi][0], a[mi][1], a[mi][2], a[mi][3],
                             b[nj >> 1][(nj & 1) * 2], b[nj >> 1][(nj & 1) * 2 + 1]);
        }
        __syncthreads();
        if (i + 2 < niter) prefetch(i + 2, buf);
        else asm volatile("cp.async.commit_group;" ::: "memory");
    }

#pragma unroll
    for (int mi = 0; mi < 4; mi++)
#pragma unroll
        for (int nj = 0; nj < 4; nj++) {
            int rl = wm * 64 + mi * 16 + (lane >> 2);
            int cl = wn * 32 + nj * 8 + (lane & 3) * 2;
            float bz0 = bias ? bias[n0 + cl] : 0.f;
            float bz1 = bias ? bias[n0 + cl + 1] : 0.f;
#pragma unroll
            for (int half2i = 0; half2i < 2; half2i++) {
                int row = m0 + rl + half2i * 8;
                float v0 = c[mi][nj][half2i * 2 + 0] + bz0;
                float v1 = c[mi][nj][half2i * 2 + 1] + bz1;
                if (act == 1) { v0 = fmaxf(v0, 0.f); v1 = fmaxf(v1, 0.f); }
                else if (act == 2) {
                    v0 = (v0 >= 0.f) ? v0 : 0.01f * v0;
                    v1 = (v1 >= 0.f) ? v1 : 0.01f * v1;
                }
                if (Cf) *(float2*)(Cf + (size_t)row * N + n0 + cl) = make_float2(v0, v1);
                if (Ch) {
                    __half2 q = __floats2half2_rn(v0, v1);
                    *(unsigned*)(Ch + (size_t)row * N + n0 + cl) = *(unsigned*)&q;
                }
            }
        }
}

// ---------------- 128x128x16 register-tiled fp32 GEMM (head) ----------------
__global__ __launch_bounds__(256, 2) void gemm128(
    const float* __restrict__ A, const float* __restrict__ B, float* __restrict__ C,
    int M, int N, int K, const float* __restrict__ bias, const float* __restrict__ Res,
    float accScale, float resScale, int act) {
    __shared__ float Ast[16 * 132];
    __shared__ float Bs[16 * 128];
    int bm = blockIdx.y, bn = blockIdx.x;
    int t = threadIdx.x;
    int tx = t & 15, ty = t >> 4;
    int arow = t >> 2, ac4 = (t & 3) << 2;
    int bkr = t >> 5, bc4 = (t & 31) << 2;
    float acc[8][8];
#pragma unroll
    for (int i = 0; i < 8; i++)
#pragma unroll
        for (int j = 0; j < 8; j++) acc[i][j] = 0.f;
    const float* Ab = A + (long long)(bm * 128) * K;
    const float* Bb = B + bn * 128;
    for (int k0 = 0; k0 < K; k0 += 16) {
        float4 a0 = *(const float4*)(Ab + (long long)arow * K + k0 + ac4);
        float4 a1 = *(const float4*)(Ab + (long long)(arow + 64) * K + k0 + ac4);
        float4 b0 = *(const float4*)(Bb + (long long)(k0 + bkr) * N + bc4);
        float4 b1 = *(const float4*)(Bb + (long long)(k0 + bkr + 8) * N + bc4);
        __syncthreads();
        Ast[(ac4 + 0) * 132 + arow] = a0.x;
        Ast[(ac4 + 1) * 132 + arow] = a0.y;
        Ast[(ac4 + 2) * 132 + arow] = a0.z;
        Ast[(ac4 + 3) * 132 + arow] = a0.w;
        Ast[(ac4 + 0) * 132 + arow + 64] = a1.x;
        Ast[(ac4 + 1) * 132 + arow + 64] = a1.y;
        Ast[(ac4 + 2) * 132 + arow + 64] = a1.z;
        Ast[(ac4 + 3) * 132 + arow + 64] = a1.w;
        *(float4*)(Bs + bkr * 128 + bc4) = b0;
        *(float4*)(Bs + (bkr + 8) * 128 + bc4) = b1;
        __syncthreads();
#pragma unroll
        for (int kk = 0; kk < 16; kk++) {
            float4 av0 = *(const float4*)(Ast + kk * 132 + ty * 8);
            float4 av1 = *(const float4*)(Ast + kk * 132 + ty * 8 + 4);
            float a[8] = {av0.x, av0.y, av0.z, av0.w, av1.x, av1.y, av1.z, av1.w};
            float b[8];
#pragma unroll
            for (int j = 0; j < 8; j++) b[j] = Bs[kk * 128 + j * 16 + tx];
#pragma unroll
            for (int i = 0; i < 8; i++)
#pragma unroll
                for (int j = 0; j < 8; j++) acc[i][j] += a[i] * b[j];
        }
    }
#pragma unroll
    for (int i = 0; i < 8; i++) {
        long long r = bm * 128 + ty * 8 + i;
#pragma unroll
        for (int j = 0; j < 8; j++) {
            int c = bn * 128 + j * 16 + tx;
            float v = accScale * acc[i][j];
            if (Res)  v += resScale * Res[r * N + c];
            if (bias) v += bias[c];
            if (act == 1) v = fmaxf(v, 0.f);
            else if (act == 2) v = (v >= 0.f) ? v : 0.01f * v;
            C[r * N + c] = v;
        }
    }
}

// ---------------- sparse structure build ----------------
__global__ void rowcnt_ext(const float* __restrict__ A, int* __restrict__ cnt,
                           float* __restrict__ dis, int* __restrict__ ccnt,
                           float* __restrict__ degsum) {
    int i = blockIdx.x;
    int tid = threadIdx.x;
    int c = 0;
    for (int j = tid; j < N_NODES; j += 256) {
        const float* ap = A + ((long long)i * N_NODES + j) * E_TYPES;
        float a[E_TYPES];
#pragma unroll
        for (int e = 0; e < E_TYPES; e++) a[e] = ap[e];
        bool nz = (j == i);
#pragma unroll
        for (int e = 0; e < E_TYPES; e++) nz |= (a[e] != 0.f);
        c += nz ? 1 : 0;
        if (j != i) {
#pragma unroll
            for (int e = 0; e < E_TYPES; e++) {
                if (a[e] != 0.f) {
                    atomicAdd(&ccnt[e * N_NODES + j], 1);
                    atomicAdd(&degsum[e * N_NODES + j], a[e]);
                }
            }
        }
    }
    __shared__ int red[256];
    red[tid] = c;
    __syncthreads();
    for (int o = 128; o; o >>= 1) {
        if (tid < o) red[tid] += red[tid + o];
        __syncthreads();
    }
    if (tid == 0) {
        cnt[i] = red[0];
        dis[i] = rsqrtf((float)red[0]);
    }
}

__global__ void scan_kernel(const int* __restrict__ cnt_base, int* __restrict__ rp_base,
                            int seg_in, int seg_out) {
    const int* cnt = cnt_base + (long long)blockIdx.x * seg_in;
    int* rowptr = rp_base + (long long)blockIdx.x * seg_out;
    __shared__ int warpsum[32];
    int t = threadIdx.x;
    int v[4], s = 0;
#pragma unroll
    for (int j = 0; j < 4; j++) { v[j] = cnt[t * 4 + j]; s += v[j]; }
    int lane = t & 31, warp = t >> 5;
    int x = s;
#pragma unroll
    for (int o = 1; o < 32; o <<= 1) {
        int y = __shfl_up_sync(0xffffffffu, x, o);
        if (lane >= o) x += y;
    }
    if (lane == 31) warpsum[warp] = x;
    __syncthreads();
    if (warp == 0) {
        int w = warpsum[lane];
#pragma unroll
        for (int o = 1; o < 32; o <<= 1) {
            int y = __shfl_up_sync(0xffffffffu, w, o);
            if (lane >= o) w += y;
        }
        warpsum[lane] = w;
    }
    __syncthreads();
    int excl = x - s + (warp ? warpsum[warp - 1] : 0);
    int run = excl;
    if (t == 0) rowptr[0] = 0;
#pragma unroll
    for (int j = 0; j < 4; j++) { run += v[j]; rowptr[t * 4 + j + 1] = run; }
}

__global__ void fill_ext(const float* __restrict__ A, const int* __restrict__ rowptr,
                         const float* __restrict__ dis, int* __restrict__ col,
                         float* __restrict__ val, const int* __restrict__ cptr,
                         int* __restrict__ cfill, int* __restrict__ csrc,
                         float* __restrict__ cval) {
    int i = blockIdx.x;
    float di = dis[i];
    __shared__ int warpCnt[8];
    __shared__ int blockBase;
    if (threadIdx.x == 0) blockBase = rowptr[i];
    __syncthreads();
    for (int j0 = 0; j0 < N_NODES; j0 += 256) {
        int j = j0 + threadIdx.x;
        const float* ap = A + ((long long)i * N_NODES + j) * E_TYPES;
        float a[E_TYPES];
#pragma unroll
        for (int e = 0; e < E_TYPES; e++) a[e] = ap[e];
        bool nz = (j == i);
#pragma unroll
        for (int e = 0; e < E_TYPES; e++) nz |= (a[e] != 0.f);
        if (j != i) {
#pragma unroll
            for (int e = 0; e < E_TYPES; e++) {
                if (a[e] != 0.f) {
                    int slot = atomicAdd(&cfill[e * N_NODES + j], 1);
                    int pos = cptr[e * (N_NODES + 1) + j] + slot;
                    csrc[e * CAPE + pos] = i;
                    cval[e * CAPE + pos] = a[e];
                }
            }
        }
        unsigned mask = __ballot_sync(0xffffffffu, nz);
        int warp = threadIdx.x >> 5, lane = threadIdx.x & 31;
        if (lane == 0) warpCnt[warp] = __popc(mask);
        __syncthreads();
        int woff = 0;
        for (int w = 0; w < warp; w++) woff += warpCnt[w];
        int total = 0;
        for (int w = 0; w < 8; w++) total += warpCnt[w];
        if (nz) {
            int pos = blockBase + woff + __popc(mask & ((1u << lane) - 1));
            col[pos] = j;
            val[pos] = di * dis[j];
        }
        __syncthreads();
        if (threadIdx.x == 0) blockBase += total;
        __syncthreads();
    }
}

// ---------------- per-row window boundaries ----------------
__global__ void window_index(const int* __restrict__ rowptr, const int* __restrict__ col,
                             int* __restrict__ wstart) {
    int t = blockIdx.x * 256 + threadIdx.x;
    if (t >= N_NODES * (NWIN + 1)) return;
    int row = t / (NWIN + 1), w = t % (NWIN + 1);
    int rs = rowptr[row], re = rowptr[row + 1];
    int res;
    if (w == 0) res = rs;
    else if (w == NWIN) res = re;
    else {
        int target = w * WINC;
        int lo = rs, hi = re;
        while (lo < hi) {
            int mid = (lo + hi) >> 1;
            if (col[mid] < target) lo = mid + 1; else hi = mid;
        }
        res = lo;
    }
    wstart[t] = res;
}

// ---------------- lgcn / attention / concat ----------------
__global__ void lgcn_csc(const float* __restrict__ Xw, const int* __restrict__ csrc,
                         const float* __restrict__ cval, const int* __restrict__ cptr,
                         const float* __restrict__ degsum, float* __restrict__ lgcn) {
    int n = blockIdx.x, e = blockIdx.y, d = threadIdx.x;
    int s = cptr[e * (N_NODES + 1) + n], en = cptr[e * (N_NODES + 1) + n + 1];
    const int* cs = csrc + (long long)e * CAPE;
    const float* cv = cval + (long long)e * CAPE;
    float acc = Xw[(long long)n * W_OUT + d];
    for (int k = s; k < en; k++)
        acc += cv[k] * Xw[(long long)cs[k] * W_OUT + d];
    float dv = 1.f / (1.f + degsum[e * N_NODES + n]);
    lgcn[((long long)e * N_NODES + n) * W_OUT + d] = fmaxf(acc * dv, 0.f);
}

__global__ void att1(const float* __restrict__ lgcn, const float* __restrict__ attw,
                     float* __restrict__ attpart) {
    int g = blockIdx.x, e = blockIdx.y, d = threadIdx.x;
    float s = 0.f;
    int n0 = g * (N_NODES / ATT_G);
    for (int n = n0; n < n0 + N_NODES / ATT_G; n++)
        s += attw[n] * lgcn[((long long)e * N_NODES + n) * W_OUT + d];
    attpart[(e * ATT_G + g) * W_OUT + d] = s;
}

__global__ void att2(const float* __restrict__ attpart, const float* __restrict__ attb,
                     const float* __restrict__ attq, float* __restrict__ beta) {
    __shared__ float red[128];
    __shared__ float w[E_TYPES];
    int d = threadIdx.x;
    for (int e = 0; e < E_TYPES; e++) {
        float tot = 0.f;
#pragma unroll 8
        for (int g = 0; g < ATT_G; g++) tot += attpart[(e * ATT_G + g) * W_OUT + d];
        red[d] = tanhf(tot + attb[d]) * attq[d];
        __syncthreads();
        for (int o = 64; o; o >>= 1) {
            if (d < o) red[d] += red[d + o];
            __syncthreads();
        }
        if (d == 0) w[e] = red[0];
        __syncthreads();
    }
    if (d == 0) {
        float mx = w[0];
        for (int e = 1; e < E_TYPES; e++) mx = fmaxf(mx, w[e]);
        float ex[E_TYPES], s = 0.f;
        for (int e = 0; e < E_TYPES; e++) { ex[e] = expf(w[e] - mx); s += ex[e]; }
        for (int e = 0; e < E_TYPES; e++) beta[e] = (float)E_TYPES * ex[e] / s;
    }
}

__global__ void xcat_kernel(const float* __restrict__ lgcn, const float* __restrict__ X,
                            const float* __restrict__ beta, __half* __restrict__ Xcat) {
    long long idx = (long long)blockIdx.x * 256 + threadIdx.x;
    long long total = (long long)N_NODES * H0;
    if (idx >= total) return;
    int n = (int)(idx / H0), c = (int)(idx % H0);
    float v;
    if (c < E_TYPES * W_OUT) {
        int e = c >> 7, d = c & 127;
        v = beta[e] * lgcn[((long long)e * N_NODES + n) * W_OUT + d];
    } else {
        v = X[(long long)n * W_IN + (c - E_TYPES * W_OUT)];
    }
    Xcat[idx] = __float2half(v);
}

// ---------------- fp32 -> fp16 convert ----------------
__global__ void f2h_kernel(const float* __restrict__ src, __half* __restrict__ dst, int n4) {
    int i = blockIdx.x * 256 + threadIdx.x;
    if (i >= n4) return;
    float4 v = ((const float4*)src)[i];
    __half2 h0 = __floats2half2_rn(v.x, v.y);
    __half2 h1 = __floats2half2_rn(v.z, v.w);
    ((float2*)dst)[i] = make_float2(h2_as_f(h0), h2_as_f(h1));
}

// ---------------- W' prep (fp32) ----------------
__global__ void wprime_prep(const float* __restrict__ W, float* __restrict__ wp) {
    int l = blockIdx.x;
    float bl = logf(0.5f / (float)(l + 1) + 1.f);
    float omb = 1.f - bl;
    const float* Wl = W + (size_t)l * W_OUT * W_OUT;
    float* o = wp + (size_t)l * W_OUT * W_OUT;
    for (int i = threadIdx.x; i < W_OUT * W_OUT; i += 256) {
        int k = i >> 7, n = i & 127;
        o[i] = bl * Wl[i] + (k == n ? omb : 0.f);
    }
}

// ---------------- windowed SpMM: part[w] = A[:, window w] @ x[window w] ----------------
// grid (NWIN, 64); block 256; smem 64KB fp16 window. thread = (row, 32-dim quarter)
__global__ __launch_bounds__(256) void spmm_win(
    const __half* __restrict__ xh, const int* __restrict__ colp,
    const float* __restrict__ valp, const int* __restrict__ wstart,
    float* __restrict__ part) {
    extern __shared__ __half xs[];        // [WINC][128]
    int w = blockIdx.x, rb = blockIdx.y;
    int t = threadIdx.x;
    {
        const uint4* src = (const uint4*)(xh + (size_t)w * WINC * W_OUT);
        uint4* dst = (uint4*)xs;
#pragma unroll
        for (int i = 0; i < 16; i++) dst[t + 256 * i] = src[t + 256 * i];
    }
    __syncthreads();
    int r = rb * 64 + (t >> 2), q = (t & 3) * 32;
    int ws = wstart[r * (NWIN + 1) + w];
    int we = wstart[r * (NWIN + 1) + w + 1];
    float acc[32];
#pragma unroll
    for (int i = 0; i < 32; i++) acc[i] = 0.f;
    int base = w * WINC;
    int k = ws;
    int cn = 0; float vn = 0.f;
    if (k < we) { cn = colp[k]; vn = valp[k]; }
    while (k < we) {
        int c = cn; float v = vn;
        k++;
        if (k < we) { cn = colp[k]; vn = valp[k]; }   // prefetch next (overlaps below)
        const uint4* xrow = (const uint4*)(xs + (size_t)(c - base) * W_OUT + q);
#pragma unroll
        for (int p = 0; p < 4; p++) {
            uint4 u = xrow[p];
            float2 f0 = __half22float2(*(__half2*)&u.x);
            float2 f1 = __half22float2(*(__half2*)&u.y);
            float2 f2 = __half22float2(*(__half2*)&u.z);
            float2 f3 = __half22float2(*(__half2*)&u.w);
            acc[p * 8 + 0] += v * f0.x; acc[p * 8 + 1] += v * f0.y;
            acc[p * 8 + 2] += v * f1.x; acc[p * 8 + 3] += v * f1.y;
            acc[p * 8 + 4] += v * f2.x; acc[p * 8 + 5] += v * f2.y;
            acc[p * 8 + 6] += v * f3.x; acc[p * 8 + 7] += v * f3.y;
        }
    }
    float* P = part + (size_t)w * N_NODES * W_OUT + (size_t)r * W_OUT + q;
#pragma unroll
    for (int p = 0; p < 8; p++)
        *(float4*)(P + p * 4) = make_float4(acc[p * 4 + 0], acc[p * 4 + 1],
                                            acc[p * 4 + 2], acc[p * 4 + 3]);
}

// ---------------- combine: h = .9*sum(part)+.1*x0; out = relu(h @ W') ----------------
// grid 128 (32-row tiles), 256 thr; warp ty owns rows ty*4.., lane cols tx*4..
__global__ __launch_bounds__(256) void combine_f32(
    const float* __restrict__ part, const float* __restrict__ x0,
    const float* __restrict__ wp, __half* __restrict__ xh_out,
    float* __restrict__ xf_out, int last) {
    __shared__ float hs[32 * 132];
    __shared__ float Ws[32 * 128];
    int t = threadIdx.x;
    int tx = t & 31, ty = t >> 5;
    int m0 = blockIdx.x * 32;
#pragma unroll
    for (int j = 0; j < 4; j++) {
        int e4 = t + 256 * j;                  // 1024 float4 = 32x128
        int r = e4 >> 5, c4 = (e4 & 31) * 4;
        size_t gi = (size_t)(m0 + r) * W_OUT + c4;
        float4 s = make_float4(0.f, 0.f, 0.f, 0.f);
#pragma unroll
        for (int sl = 0; sl < NWIN; sl++) {
            float4 p = *(const float4*)(part + (size_t)sl * N_NODES * W_OUT + gi);
            s.x += p.x; s.y += p.y; s.z += p.z; s.w += p.w;
        }
        float4 xv = *(const float4*)(x0 + gi);
        float4 h;
        h.x = 0.9f * s.x + 0.1f * xv.x;
        h.y = 0.9f * s.y + 0.1f * xv.y;
        h.z = 0.9f * s.z + 0.1f * xv.z;
        h.w = 0.9f * s.w + 0.1f * xv.w;
        *(float4*)(hs + r * 132 + c4) = h;
    }
    float acc[4][4];
#pragma unroll
    for (int i = 0; i < 4; i++)
#pragma unroll
        for (int q = 0; q < 4; q++) acc[i][q] = 0.f;
    for (int k0 = 0; k0 < 128; k0 += 32) {
        __syncthreads();                       // first iter also publishes hs
#pragma unroll
        for (int j = 0; j < 4; j++) {
            int idx = t + 256 * j;             // 1024 float4 = 32x128
            int r = idx >> 5, c4 = (idx & 31) * 4;
            *(float4*)(Ws + r * 128 + c4) = *(const float4*)(wp + (k0 + r) * W_OUT + c4);
        }
        __syncthreads();
#pragma unroll
        for (int kk = 0; kk < 32; kk++) {
            float4 b = *(const float4*)(Ws + kk * 128 + tx * 4);
#pragma unroll
            for (int i = 0; i < 4; i++) {
                float a = hs[(ty * 4 + i) * 132 + k0 + kk];
                acc[i][0] += a * b.x; acc[i][1] += a * b.y;
                acc[i][2] += a * b.z; acc[i][3] += a * b.w;
            }
        }
    }
#pragma unroll
    for (int i = 0; i < 4; i++) {
        int row = m0 + ty * 4 + i;
        float v0 = fmaxf(acc[i][0], 0.f), v1 = fmaxf(acc[i][1], 0.f);
        float v2 = fmaxf(acc[i][2], 0.f), v3 = fmaxf(acc[i][3], 0.f);
        if (last) {
            *(float4*)(xf_out + (size_t)row * W_OUT + tx * 4) = make_float4(v0, v1, v2, v3);
        } else {
            __half2 q0 = __floats2half2_rn(v0, v1);
            __half2 q1 = __floats2half2_rn(v2, v3);
            *(float2*)(xh_out + (size_t)row * W_OUT + tx * 4) =
                make_float2(h2_as_f(q0), h2_as_f(q1));
        }
    }
}

// ---------------- head ----------------
__global__ void out_kernel(const float* __restrict__ Z, const int* __restrict__ tx,
                           const float* __restrict__ W2, const float* __restrict__ b2,
                           float* __restrict__ y) {
    int r = blockIdx.x;
    int t = threadIdx.x;
    __shared__ float z[W_OUT];
    z[t] = Z[(long long)tx[r] * W_OUT + t];
    __syncthreads();
    if (t < NUM_CLASS) {
        float s = b2[t];
        for (int k = 0; k < W_OUT; k++) s += z[k] * W2[k * NUM_CLASS + t];
        y[r * NUM_CLASS + t] = s;
    }
}

__global__ void loss_kernel(const float* __restrict__ y, const int* __restrict__ target,
                            float* __restrict__ out) {
    __shared__ float red[256];
    int tid = threadIdx.x;
    float part = 0.f;
    for (int r = tid; r < M_TGT; r += 256) {
        const float* yr = y + r * NUM_CLASS;
        float mx = yr[0];
#pragma unroll
        for (int c = 1; c < NUM_CLASS; c++) mx = fmaxf(mx, yr[c]);
        float se = 0.f;
#pragma unroll
        for (int c = 0; c < NUM_CLASS; c++) se += expf(yr[c] - mx);
        float lse = mx + logf(se);
        part += lse - yr[target[r]];
    }
    red[tid] = part;
    __syncthreads();
    for (int o = 128; o; o >>= 1) {
        if (tid < o) red[tid] += red[tid + o];
        __syncthreads();
    }
    if (tid == 0) out[0] = red[0] / (float)M_TGT;
}

// ---------------- launch ----------------
extern "C" void kernel_launch(void* const* d_in, const int* in_sizes, int n_in,
                              void* d_out, int out_size) {
    const float* A        = (const float*)d_in[0];
    const float* X        = (const float*)d_in[1];
    const int*   target_x = (const int*)d_in[2];
    const int*   target   = (const int*)d_in[3];
    const float* weight   = (const float*)d_in[4];
    const float* attw     = (const float*)d_in[5];
    const float* attb     = (const float*)d_in[6];
    const float* attq     = (const float*)d_in[7];
    const float* Wg       = (const float*)d_in[8];
    const float* bg       = (const float*)d_in[9];
    const float* W0       = (const float*)d_in[10];
    const float* b0       = (const float*)d_in[11];
    const float* Wconvs   = (const float*)d_in[12];
    const float* Wd1      = (const float*)d_in[13];
    const float* bd1      = (const float*)d_in[14];
    const float* W1       = (const float*)d_in[15];
    const float* b1       = (const float*)d_in[16];
    const float* W2       = (const float*)d_in[17];
    const float* b2       = (const float*)d_in[18];

    float *Xw, *lgcn, *attpart, *beta, *x0, *xlast, *Z1, *Z2, *ybuf;
    float *dis, *valp, *cvalp, *wp, *partp;
    __half *Xh, *Wgh, *weighth, *W0h, *Xgh, *Xcath, *xh0, *xhA, *xhB;
    int *cnt, *rowptr, *colp, *zinit, *cptr, *csrcp, *wst;
    cudaGetSymbolAddress((void**)&Xh, g_Xh);
    cudaGetSymbolAddress((void**)&Wgh, g_Wgh);
    cudaGetSymbolAddress((void**)&weighth, g_weighth);
    cudaGetSymbolAddress((void**)&W0h, g_W0h);
    cudaGetSymbolAddress((void**)&Xgh, g_Xgh);
    cudaGetSymbolAddress((void**)&Xw, g_Xw);
    cudaGetSymbolAddress((void**)&lgcn, g_lgcn);
    cudaGetSymbolAddress((void**)&attpart, g_attpart);
    cudaGetSymbolAddress((void**)&beta, g_beta);
    cudaGetSymbolAddress((void**)&Xcath, g_Xcath);
    cudaGetSymbolAddress((void**)&x0, g_x0);
    cudaGetSymbolAddress((void**)&xlast, g_xlast);
    cudaGetSymbolAddress((void**)&xh0, g_xh0);
    cudaGetSymbolAddress((void**)&xhA, g_xhA);
    cudaGetSymbolAddress((void**)&xhB, g_xhB);
    cudaGetSymbolAddress((void**)&wp, g_wprime);
    cudaGetSymbolAddress((void**)&partp, g_part);
    cudaGetSymbolAddress((void**)&wst, g_wstart);
    cudaGetSymbolAddress((void**)&Z1, g_Z1);
    cudaGetSymbolAddress((void**)&Z2, g_Z2);
    cudaGetSymbolAddress((void**)&ybuf, g_y);
    cudaGetSymbolAddress((void**)&cnt, g_cnt);
    cudaGetSymbolAddress((void**)&rowptr, g_rowptr);
    cudaGetSymbolAddress((void**)&dis, g_dis);
    cudaGetSymbolAddress((void**)&colp, g_col);
    cudaGetSymbolAddress((void**)&valp, g_val);
    cudaGetSymbolAddress((void**)&zinit, g_zinit);
    cudaGetSymbolAddress((void**)&cptr, g_cptr);
    cudaGetSymbolAddress((void**)&csrcp, g_csrc);
    cudaGetSymbolAddress((void**)&cvalp, g_cval);

    int* ccnt = zinit;
    int* cfill = zinit + E_TYPES * N_NODES;
    float* degsum = (float*)(zinit + 2 * E_TYPES * N_NODES);

    cudaFuncSetAttribute(spmm_win, cudaFuncAttributeMaxDynamicSharedMemorySize, 65536);

    cudaMemsetAsync(zinit, 0, 3 * E_TYPES * N_NODES * sizeof(int));

    // 0) fp16 conversions of GEMM operands
    f2h_kernel<<<(N_NODES * W_IN / 4 + 255) / 256, 256>>>(X, Xh, N_NODES * W_IN / 4);
    f2h_kernel<<<(W_IN * W_IN / 4 + 255) / 256, 256>>>(Wg, Wgh, W_IN * W_IN / 4);
    f2h_kernel<<<(W_IN * W_OUT / 4 + 255) / 256, 256>>>(weight, weighth, W_IN * W_OUT / 4);
    f2h_kernel<<<(H0 * W_OUT / 4 + 255) / 256, 256>>>(W0, W0h, H0 * W_OUT / 4);

    // 1) Xg = leaky(X@Wg+bg) [fp16], Xw = leaky(Xg@weight) [fp32]  — HMMA
    hgemm<<<dim3(N_NODES / 128, W_IN / 128), 256>>>(Xh, Wgh, N_NODES, W_IN, W_IN,
                                                    bg, 2, nullptr, Xgh);
    hgemm<<<dim3(N_NODES / 128, 1), 256>>>(Xgh, weighth, N_NODES, W_OUT, W_IN,
                                           nullptr, 2, Xw, nullptr);
    // 2) sparse structure + W' prep + window index
    rowcnt_ext<<<N_NODES, 256>>>(A, cnt, dis, ccnt, degsum);
    scan_kernel<<<1, 1024>>>(cnt, rowptr, 0, 0);
    scan_kernel<<<E_TYPES, 1024>>>(ccnt, cptr, N_NODES, N_NODES + 1);
    fill_ext<<<N_NODES, 256>>>(A, rowptr, dis, colp, valp, cptr, cfill, csrcp, cvalp);
    window_index<<<(N_NODES * (NWIN + 1) + 255) / 256, 256>>>(rowptr, colp, wst);
    wprime_prep<<<NUM_LAYERS, 256>>>(Wconvs, wp);
    // 3) lgcn + attention + concat + x0 (HMMA W0 GEMM emits fp32 + fp16)
    lgcn_csc<<<dim3(N_NODES, E_TYPES), 128>>>(Xw, csrcp, cvalp, cptr, degsum, lgcn);
    att1<<<dim3(ATT_G, E_TYPES), 128>>>(lgcn, attw, attpart);
    att2<<<1, 128>>>(attpart, attb, attq, beta);
    {
        long long total = (long long)N_NODES * H0;
        xcat_kernel<<<(unsigned)((total + 255) / 256), 256>>>(lgcn, X, beta, Xcath);
    }
    hgemm<<<dim3(N_NODES / 128, 1), 256>>>(Xcath, W0h, N_NODES, W_OUT, H0,
                                           b0, 1, x0, xh0);
    // 4) 64 GCNII layers: windowed SpMM + fused combine
    const __half* xin = xh0;
    __half* bufs[2] = {xhA, xhB};
    for (int l = 0; l < NUM_LAYERS; l++) {
        bool last = (l == NUM_LAYERS - 1);
        __half* xh = bufs[l & 1];
        spmm_win<<<dim3(NWIN, N_NODES / 64), 256, 65536>>>(xin, colp, valp, wst, partp);
        combine_f32<<<N_NODES / 32, 256>>>(partp, x0, wp + (size_t)l * W_OUT * W_OUT,
                                           xh, xlast, last ? 1 : 0);
        xin = xh;
    }
    // 5) head (fp32)
    gemm128<<<dim3(1, N_NODES / 128), 256>>>(xlast, Wd1, Z1, N_NODES, W_OUT, W_OUT,
                                             bd1, nullptr, 1.f, 0.f, 2);
    gemm128<<<dim3(1, N_NODES / 128), 256>>>(Z1, W1, Z2, N_NODES, W_OUT, W_OUT,
                                             b1, nullptr, 1.f, 0.f, 2);
    float* yout;
    bool with_loss;
    if (out_size >= M_TGT * NUM_CLASS + 1) { yout = (float*)d_out + 1; with_loss = true; }
    else if (out_size == M_TGT * NUM_CLASS) { yout = (float*)d_out; with_loss = false; }
    else { yout = ybuf; with_loss = true; }
    out_kernel<<<M_TGT, 128>>>(Z2, target_x, W2, b2, yout);
    if (with_loss) loss_kernel<<<1, 256>>>(yout, target, (float*)d_out);
}

// round 14
// speedup vs baseline: 1.5773x; 1.5773x over previous
#include <cuda_runtime.h>
#include <cuda_fp16.h>
#include <math.h>
#include <stdint.h>

#define N_NODES 4096
#define E_TYPES 5
#define W_IN 512
#define W_OUT 128
#define NUM_CLASS 16
#define M_TGT 1024
#define NUM_LAYERS 64
#define H0 (W_IN + E_TYPES * W_OUT)   // 1152
#define NNZ_CAP 2097152
#define CAPE 262144
#define ATT_G 128

// ---------------- static scratch ----------------
__device__ __half g_Xh[N_NODES * W_IN];
__device__ __half g_Wgh[W_IN * W_IN];
__device__ __half g_weighth[W_IN * W_OUT];
__device__ __half g_W0h[H0 * W_OUT];
__device__ __half g_Wd1h[W_OUT * W_OUT];
__device__ __half g_W1h[W_OUT * W_OUT];
__device__ __half g_Xgh[N_NODES * W_IN];
__device__ __half g_Xwh[N_NODES * W_OUT];        // Xw fp16 (lgcn gather source)
__device__ float g_lgcn[E_TYPES * N_NODES * W_OUT];
__device__ float g_attpart[E_TYPES * ATT_G * W_OUT];
__device__ float g_beta[E_TYPES];
__device__ __half g_Xcath[N_NODES * H0];
__device__ float g_x0[N_NODES * W_OUT];
__device__ __half g_xlasth[N_NODES * W_OUT];
__device__ __half g_xh0[N_NODES * W_OUT];
__device__ __half g_xhA[N_NODES * W_OUT];
__device__ __half g_xhB[N_NODES * W_OUT];
__device__ __half g_Z1h[N_NODES * W_OUT];
__device__ float g_Z2[N_NODES * W_OUT];
__device__ float g_y[M_TGT * NUM_CLASS];
__device__ int   g_cnt[N_NODES];
__device__ int   g_rowptr[N_NODES + 1];
__device__ float g_dis[N_NODES];
__device__ int   g_col[NNZ_CAP];
__device__ float g_val[NNZ_CAP];
__device__ int   g_zinit[3 * E_TYPES * N_NODES];
__device__ int   g_cptr[E_TYPES * (N_NODES + 1)];
__device__ int   g_csrc[E_TYPES * CAPE];
__device__ float g_cval[E_TYPES * CAPE];

// ---------------- helpers ----------------
__device__ __forceinline__ float h2_as_f(__half2 h) {
    return __uint_as_float(*(unsigned*)&h);
}
__device__ __forceinline__ uint32_t smem_u32(const void* p) {
    uint32_t a;
    asm("{ .reg .u64 t; cvta.to.shared.u64 t, %1; cvt.u32.u64 %0, t; }" : "=r"(a) : "l"(p));
    return a;
}
__device__ __forceinline__ void cpa16(uint32_t dst, const void* src) {
    asm volatile("cp.async.cg.shared.global [%0], [%1], 16;" :: "r"(dst), "l"(src));
}
__device__ __forceinline__ void ldmx4(uint32_t& r0, uint32_t& r1, uint32_t& r2,
                                      uint32_t& r3, uint32_t addr) {
    asm volatile("ldmatrix.sync.aligned.m8n8.x4.shared.b16 {%0,%1,%2,%3}, [%4];"
                 : "=r"(r0), "=r"(r1), "=r"(r2), "=r"(r3) : "r"(addr));
}
__device__ __forceinline__ void ldmx4t(uint32_t& r0, uint32_t& r1, uint32_t& r2,
                                       uint32_t& r3, uint32_t addr) {
    asm volatile("ldmatrix.sync.aligned.m8n8.x4.trans.shared.b16 {%0,%1,%2,%3}, [%4];"
                 : "=r"(r0), "=r"(r1), "=r"(r2), "=r"(r3) : "r"(addr));
}
__device__ __forceinline__ void mma16816(float* c, uint32_t a0, uint32_t a1, uint32_t a2,
                                         uint32_t a3, uint32_t b0, uint32_t b1) {
    asm volatile(
        "mma.sync.aligned.m16n8k16.row.col.f32.f16.f16.f32 "
        "{%0,%1,%2,%3}, {%4,%5,%6,%7}, {%8,%9}, {%0,%1,%2,%3};"
        : "+f"(c[0]), "+f"(c[1]), "+f"(c[2]), "+f"(c[3])
        : "r"(a0), "r"(a1), "r"(a2), "r"(a3), "r"(b0), "r"(b1));
}

// ---------------- generic fp16 HMMA GEMM with epilogue ----------------
// C[M,N] = act(A_h[M,K] @ B_h[K,N] + bias), act: 0 none, 1 relu, 2 leaky
__global__ __launch_bounds__(256, 1) void hgemm(
    const __half* __restrict__ A, const __half* __restrict__ B,
    int M, int N, int K, const float* __restrict__ bias, int act,
    float* __restrict__ Cf, __half* __restrict__ Ch) {
    __shared__ __half As[2][128 * 40];
    __shared__ __half Bs[2][32 * 136];
    int t = threadIdx.x, w = t >> 5, lane = t & 31;
    int m0 = blockIdx.x * 128, n0 = blockIdx.y * 128;
    const __half* Ag = A + (size_t)m0 * K;
    const __half* Bg = B + n0;
    uint32_t asb[2] = {smem_u32(As[0]), smem_u32(As[1])};
    uint32_t bsb[2] = {smem_u32(Bs[0]), smem_u32(Bs[1])};

    auto prefetch = [&](int i, int buf) {
#pragma unroll
        for (int j = 0; j < 2; j++) {
            int cid = t + 256 * j;
            int r = cid >> 2, co = (cid & 3) * 8;
            cpa16(asb[buf] + (r * 40 + co) * 2, Ag + (size_t)r * K + i * 32 + co);
            int rb = cid >> 4, cb = (cid & 15) * 8;
            cpa16(bsb[buf] + (rb * 136 + cb) * 2, Bg + (size_t)(i * 32 + rb) * N + cb);
        }
        asm volatile("cp.async.commit_group;" ::: "memory");
    };
    prefetch(0, 0);
    prefetch(1, 1);

    int wm = w >> 2, wn = w & 3;
    float c[4][4][4];
#pragma unroll
    for (int mi = 0; mi < 4; mi++)
#pragma unroll
        for (int nj = 0; nj < 4; nj++)
#pragma unroll
            for (int q = 0; q < 4; q++) c[mi][nj][q] = 0.f;

    int niter = K / 32;
    for (int i = 0; i < niter; i++) {
        asm volatile("cp.async.wait_group 1;" ::: "memory");
        __syncthreads();
        int buf = i & 1;
        uint32_t ab = asb[buf], bb = bsb[buf];
#pragma unroll
        for (int kk = 0; kk < 2; kk++) {
            uint32_t a[4][4];
#pragma unroll
            for (int mi = 0; mi < 4; mi++) {
                int row = wm * 64 + mi * 16 + (lane & 15);
                int col = kk * 16 + (lane >> 4) * 8;
                ldmx4(a[mi][0], a[mi][1], a[mi][2], a[mi][3], ab + (row * 40 + col) * 2);
            }
            uint32_t b[2][4];
#pragma unroll
            for (int ng = 0; ng < 2; ng++) {
                int row = kk * 16 + (lane & 15);
                int col = wn * 32 + ng * 16 + (lane >> 4) * 8;
                ldmx4t(b[ng][0], b[ng][1], b[ng][2], b[ng][3], bb + (row * 136 + col) * 2);
            }
#pragma unroll
            for (int mi = 0; mi < 4; mi++)
#pragma unroll
                for (int nj = 0; nj < 4; nj++)
                    mma16816(c[mi][nj], a[mi][0], a[mi][1], a[mi][2], a[mi][3],
                             b[nj >> 1][(nj & 1) * 2], b[nj >> 1][(nj & 1) * 2 + 1]);
        }
        __syncthreads();
        if (i + 2 < niter) prefetch(i + 2, buf);
        else asm volatile("cp.async.commit_group;" ::: "memory");
    }

#pragma unroll
    for (int mi = 0; mi < 4; mi++)
#pragma unroll
        for (int nj = 0; nj < 4; nj++) {
            int rl = wm * 64 + mi * 16 + (lane >> 2);
            int cl = wn * 32 + nj * 8 + (lane & 3) * 2;
            float bz0 = bias ? bias[n0 + cl] : 0.f;
            float bz1 = bias ? bias[n0 + cl + 1] : 0.f;
#pragma unroll
            for (int half2i = 0; half2i < 2; half2i++) {
                int row = m0 + rl + half2i * 8;
                float v0 = c[mi][nj][half2i * 2 + 0] + bz0;
                float v1 = c[mi][nj][half2i * 2 + 1] + bz1;
                if (act == 1) { v0 = fmaxf(v0, 0.f); v1 = fmaxf(v1, 0.f); }
                else if (act == 2) {
                    v0 = (v0 >= 0.f) ? v0 : 0.01f * v0;
                    v1 = (v1 >= 0.f) ? v1 : 0.01f * v1;
                }
                if (Cf) *(float2*)(Cf + (size_t)row * N + n0 + cl) = make_float2(v0, v1);
                if (Ch) {
                    __half2 q = __floats2half2_rn(v0, v1);
                    *(unsigned*)(Ch + (size_t)row * N + n0 + cl) = *(unsigned*)&q;
                }
            }
        }
}

// ---------------- sparse structure build ----------------
__global__ void rowcnt_ext(const float* __restrict__ A, int* __restrict__ cnt,
                           float* __restrict__ dis, int* __restrict__ ccnt,
                           float* __restrict__ degsum) {
    int i = blockIdx.x;
    int tid = threadIdx.x;
    int c = 0;
    for (int j = tid; j < N_NODES; j += 256) {
        const float* ap = A + ((long long)i * N_NODES + j) * E_TYPES;
        float a[E_TYPES];
#pragma unroll
        for (int e = 0; e < E_TYPES; e++) a[e] = ap[e];
        bool nz = (j == i);
#pragma unroll
        for (int e = 0; e < E_TYPES; e++) nz |= (a[e] != 0.f);
        c += nz ? 1 : 0;
        if (j != i) {
#pragma unroll
            for (int e = 0; e < E_TYPES; e++) {
                if (a[e] != 0.f) {
                    atomicAdd(&ccnt[e * N_NODES + j], 1);
                    atomicAdd(&degsum[e * N_NODES + j], a[e]);
                }
            }
        }
    }
    __shared__ int red[256];
    red[tid] = c;
    __syncthreads();
    for (int o = 128; o; o >>= 1) {
        if (tid < o) red[tid] += red[tid + o];
        __syncthreads();
    }
    if (tid == 0) {
        cnt[i] = red[0];
        dis[i] = rsqrtf((float)red[0]);
    }
}

__global__ void scan_kernel(const int* __restrict__ cnt_base, int* __restrict__ rp_base,
                            int seg_in, int seg_out) {
    const int* cnt = cnt_base + (long long)blockIdx.x * seg_in;
    int* rowptr = rp_base + (long long)blockIdx.x * seg_out;
    __shared__ int warpsum[32];
    int t = threadIdx.x;
    int v[4], s = 0;
#pragma unroll
    for (int j = 0; j < 4; j++) { v[j] = cnt[t * 4 + j]; s += v[j]; }
    int lane = t & 31, warp = t >> 5;
    int x = s;
#pragma unroll
    for (int o = 1; o < 32; o <<= 1) {
        int y = __shfl_up_sync(0xffffffffu, x, o);
        if (lane >= o) x += y;
    }
    if (lane == 31) warpsum[warp] = x;
    __syncthreads();
    if (warp == 0) {
        int w = warpsum[lane];
#pragma unroll
        for (int o = 1; o < 32; o <<= 1) {
            int y = __shfl_up_sync(0xffffffffu, w, o);
            if (lane >= o) w += y;
        }
        warpsum[lane] = w;
    }
    __syncthreads();
    int excl = x - s + (warp ? warpsum[warp - 1] : 0);
    int run = excl;
    if (t == 0) rowptr[0] = 0;
#pragma unroll
    for (int j = 0; j < 4; j++) { run += v[j]; rowptr[t * 4 + j + 1] = run; }
}

__global__ void fill_ext(const float* __restrict__ A, const int* __restrict__ rowptr,
                         const float* __restrict__ dis, int* __restrict__ col,
                         float* __restrict__ val, const int* __restrict__ cptr,
                         int* __restrict__ cfill, int* __restrict__ csrc,
                         float* __restrict__ cval) {
    int i = blockIdx.x;
    float di = dis[i];
    __shared__ int warpCnt[8];
    __shared__ int blockBase;
    if (threadIdx.x == 0) blockBase = rowptr[i];
    __syncthreads();
    for (int j0 = 0; j0 < N_NODES; j0 += 256) {
        int j = j0 + threadIdx.x;
        const float* ap = A + ((long long)i * N_NODES + j) * E_TYPES;
        float a[E_TYPES];
#pragma unroll
        for (int e = 0; e < E_TYPES; e++) a[e] = ap[e];
        bool nz = (j == i);
#pragma unroll
        for (int e = 0; e < E_TYPES; e++) nz |= (a[e] != 0.f);
        if (j != i) {
#pragma unroll
            for (int e = 0; e < E_TYPES; e++) {
                if (a[e] != 0.f) {
                    int slot = atomicAdd(&cfill[e * N_NODES + j], 1);
                    int pos = cptr[e * (N_NODES + 1) + j] + slot;
                    csrc[e * CAPE + pos] = i;
                    cval[e * CAPE + pos] = a[e];
                }
            }
        }
        unsigned mask = __ballot_sync(0xffffffffu, nz);
        int warp = threadIdx.x >> 5, lane = threadIdx.x & 31;
        if (lane == 0) warpCnt[warp] = __popc(mask);
        __syncthreads();
        int woff = 0;
        for (int w = 0; w < warp; w++) woff += warpCnt[w];
        int total = 0;
        for (int w = 0; w < 8; w++) total += warpCnt[w];
        if (nz) {
            int pos = blockBase + woff + __popc(mask & ((1u << lane) - 1));
            col[pos] = j;
            val[pos] = di * dis[j];
        }
        __syncthreads();
        if (threadIdx.x == 0) blockBase += total;
        __syncthreads();
    }
}

// ---------------- lgcn via per-e CSC gather (fp16 source) ----------------
__global__ void lgcn_csc(const __half* __restrict__ Xwh, const int* __restrict__ csrc,
                         const float* __restrict__ cval, const int* __restrict__ cptr,
                         const float* __restrict__ degsum, float* __restrict__ lgcn) {
    int n = blockIdx.x, e = blockIdx.y, d = threadIdx.x;
    int s = cptr[e * (N_NODES + 1) + n], en = cptr[e * (N_NODES + 1) + n + 1];
    const int* cs = csrc + (long long)e * CAPE;
    const float* cv = cval + (long long)e * CAPE;
    float acc = __half2float(Xwh[(long long)n * W_OUT + d]);
    for (int k = s; k < en; k++)
        acc += cv[k] * __half2float(Xwh[(long long)cs[k] * W_OUT + d]);
    float dv = 1.f / (1.f + degsum[e * N_NODES + n]);
    lgcn[((long long)e * N_NODES + n) * W_OUT + d] = fmaxf(acc * dv, 0.f);
}

__global__ void att1(const float* __restrict__ lgcn, const float* __restrict__ attw,
                     float* __restrict__ attpart) {
    int g = blockIdx.x, e = blockIdx.y, d = threadIdx.x;
    float s = 0.f;
    int n0 = g * (N_NODES / ATT_G);
    for (int n = n0; n < n0 + N_NODES / ATT_G; n++)
        s += attw[n] * lgcn[((long long)e * N_NODES + n) * W_OUT + d];
    attpart[(e * ATT_G + g) * W_OUT + d] = s;
}

__global__ void att2(const float* __restrict__ attpart, const float* __restrict__ attb,
                     const float* __restrict__ attq, float* __restrict__ beta) {
    __shared__ float red[128];
    __shared__ float w[E_TYPES];
    int d = threadIdx.x;
    for (int e = 0; e < E_TYPES; e++) {
        float tot = 0.f;
#pragma unroll 8
        for (int g = 0; g < ATT_G; g++) tot += attpart[(e * ATT_G + g) * W_OUT + d];
        red[d] = tanhf(tot + attb[d]) * attq[d];
        __syncthreads();
        for (int o = 64; o; o >>= 1) {
            if (d < o) red[d] += red[d + o];
            __syncthreads();
        }
        if (d == 0) w[e] = red[0];
        __syncthreads();
    }
    if (d == 0) {
        float mx = w[0];
        for (int e = 1; e < E_TYPES; e++) mx = fmaxf(mx, w[e]);
        float ex[E_TYPES], s = 0.f;
        for (int e = 0; e < E_TYPES; e++) { ex[e] = expf(w[e] - mx); s += ex[e]; }
        for (int e = 0; e < E_TYPES; e++) beta[e] = (float)E_TYPES * ex[e] / s;
    }
}

// X_ = [beta*lgcn (e-major) | X] in fp16
__global__ void xcat_kernel(const float* __restrict__ lgcn, const float* __restrict__ X,
                            const float* __restrict__ beta, __half* __restrict__ Xcat) {
    long long idx = (long long)blockIdx.x * 256 + threadIdx.x;
    long long total = (long long)N_NODES * H0;
    if (idx >= total) return;
    int n = (int)(idx / H0), c = (int)(idx % H0);
    float v;
    if (c < E_TYPES * W_OUT) {
        int e = c >> 7, d = c & 127;
        v = beta[e] * lgcn[((long long)e * N_NODES + n) * W_OUT + d];
    } else {
        v = X[(long long)n * W_IN + (c - E_TYPES * W_OUT)];
    }
    Xcat[idx] = __float2half(v);
}

// ---------------- fp32 -> fp16 convert ----------------
__global__ void f2h_kernel(const float* __restrict__ src, __half* __restrict__ dst, int n4) {
    int i = blockIdx.x * 256 + threadIdx.x;
    if (i >= n4) return;
    float4 v = ((const float4*)src)[i];
    __half2 h0 = __floats2half2_rn(v.x, v.y);
    __half2 h1 = __floats2half2_rn(v.z, v.w);
    ((float2*)dst)[i] = make_float2(h2_as_f(h0), h2_as_f(h1));
}

// ---------------- fused GCNII layer, 4 rows/block, 2 warps/row (proven) ----------------
__global__ __launch_bounds__(256) void layer_fused4(
    const int* __restrict__ rowptr, const int* __restrict__ colp,
    const float* __restrict__ valp, const __half* __restrict__ xh,
    const float* __restrict__ x0, const float* __restrict__ Wl, float bl,
    __half* __restrict__ xh_out) {
    __shared__ float hs[4][132];
    __shared__ float ps[4][128];
    __shared__ float Bs[32 * 128];
    int t = threadIdx.x;
    int warp = t >> 5, lane = t & 31;
    int rloc = warp >> 1, half = warp & 1;
    int row = blockIdx.x * 4 + rloc;
    int ks = rowptr[row], ke = rowptr[row + 1];
    float a0 = 0.f, a1 = 0.f, a2 = 0.f, a3 = 0.f;
    for (int k0 = ks + half * 32; k0 < ke; k0 += 64) {
        int cnt = min(32, ke - k0);
        int cR = 0; float vR = 0.f;
        if (lane < cnt) { cR = colp[k0 + lane]; vR = valp[k0 + lane]; }
#pragma unroll 4
        for (int kk = 0; kk < cnt; kk++) {
            int c = __shfl_sync(0xffffffffu, cR, kk);
            float v = __shfl_sync(0xffffffffu, vR, kk);
            float2 raw = ((const float2*)(xh + (long long)c * W_OUT))[lane];
            __half2 p0 = *(__half2*)&raw.x;
            __half2 p1 = *(__half2*)&raw.y;
            float2 f0 = __half22float2(p0);
            float2 f1 = __half22float2(p1);
            a0 += v * f0.x; a1 += v * f0.y; a2 += v * f1.x; a3 += v * f1.y;
        }
    }
    if (half) {
        ps[rloc][lane * 4 + 0] = a0;
        ps[rloc][lane * 4 + 1] = a1;
        ps[rloc][lane * 4 + 2] = a2;
        ps[rloc][lane * 4 + 3] = a3;
    }
    __syncthreads();
    if (!half) {
        const float4 xv = ((const float4*)(x0 + (long long)row * W_OUT))[lane];
        hs[rloc][lane * 4 + 0] = 0.9f * (a0 + ps[rloc][lane * 4 + 0]) + 0.1f * xv.x;
        hs[rloc][lane * 4 + 1] = 0.9f * (a1 + ps[rloc][lane * 4 + 1]) + 0.1f * xv.y;
        hs[rloc][lane * 4 + 2] = 0.9f * (a2 + ps[rloc][lane * 4 + 2]) + 0.1f * xv.z;
        hs[rloc][lane * 4 + 3] = 0.9f * (a3 + ps[rloc][lane * 4 + 3]) + 0.1f * xv.w;
    }
    int cb = half * 64 + lane * 2;
    float acc0 = 0.f, acc1 = 0.f;
    for (int k0 = 0; k0 < 128; k0 += 32) {
        __syncthreads();
#pragma unroll
        for (int i = 0; i < 4; i++) {
            int idx = t + 256 * i;
            int br = idx >> 5, bc = (idx & 31) << 2;
            *(float4*)(Bs + br * 128 + bc) = *(const float4*)(Wl + (long long)(k0 + br) * W_OUT + bc);
        }
        __syncthreads();
#pragma unroll
        for (int kk = 0; kk < 32; kk++) {
            float a = hs[rloc][k0 + kk];
            float2 b = *(const float2*)(Bs + kk * 128 + cb);
            acc0 += a * b.x; acc1 += a * b.y;
        }
    }
    float omb = 1.f - bl;
    float h0 = hs[rloc][cb], h1 = hs[rloc][cb + 1];
    float o0 = fmaxf(bl * acc0 + omb * h0, 0.f);
    float o1 = fmaxf(bl * acc1 + omb * h1, 0.f);
    __half2 q = __floats2half2_rn(o0, o1);
    *(unsigned*)(xh_out + (long long)row * W_OUT + cb) = *(unsigned*)&q;
}

// ---------------- head ----------------
__global__ void out_kernel(const float* __restrict__ Z, const int* __restrict__ tx,
                           const float* __restrict__ W2, const float* __restrict__ b2,
                           float* __restrict__ y) {
    int r = blockIdx.x;
    int t = threadIdx.x;
    __shared__ float z[W_OUT];
    z[t] = Z[(long long)tx[r] * W_OUT + t];
    __syncthreads();
    if (t < NUM_CLASS) {
        float s = b2[t];
        for (int k = 0; k < W_OUT; k++) s += z[k] * W2[k * NUM_CLASS + t];
        y[r * NUM_CLASS + t] = s;
    }
}

__global__ void loss_kernel(const float* __restrict__ y, const int* __restrict__ target,
                            float* __restrict__ out) {
    __shared__ float red[256];
    int tid = threadIdx.x;
    float part = 0.f;
    for (int r = tid; r < M_TGT; r += 256) {
        const float* yr = y + r * NUM_CLASS;
        float mx = yr[0];
#pragma unroll
        for (int c = 1; c < NUM_CLASS; c++) mx = fmaxf(mx, yr[c]);
        float se = 0.f;
#pragma unroll
        for (int c = 0; c < NUM_CLASS; c++) se += expf(yr[c] - mx);
        float lse = mx + logf(se);
        part += lse - yr[target[r]];
    }
    red[tid] = part;
    __syncthreads();
    for (int o = 128; o; o >>= 1) {
        if (tid < o) red[tid] += red[tid + o];
        __syncthreads();
    }
    if (tid == 0) out[0] = red[0] / (float)M_TGT;
}

// ---------------- launch ----------------
extern "C" void kernel_launch(void* const* d_in, const int* in_sizes, int n_in,
                              void* d_out, int out_size) {
    const float* A        = (const float*)d_in[0];
    const float* X        = (const float*)d_in[1];
    const int*   target_x = (const int*)d_in[2];
    const int*   target   = (const int*)d_in[3];
    const float* weight   = (const float*)d_in[4];
    const float* attw     = (const float*)d_in[5];
    const float* attb     = (const float*)d_in[6];
    const float* attq     = (const float*)d_in[7];
    const float* Wg       = (const float*)d_in[8];
    const float* bg       = (const float*)d_in[9];
    const float* W0       = (const float*)d_in[10];
    const float* b0       = (const float*)d_in[11];
    const float* Wconvs   = (const float*)d_in[12];
    const float* Wd1      = (const float*)d_in[13];
    const float* bd1      = (const float*)d_in[14];
    const float* W1       = (const float*)d_in[15];
    const float* b1       = (const float*)d_in[16];
    const float* W2       = (const float*)d_in[17];
    const float* b2       = (const float*)d_in[18];

    float *lgcn, *attpart, *beta, *x0, *Z2, *ybuf;
    float *dis, *valp, *cvalp;
    __half *Xh, *Wgh, *weighth, *W0h, *Wd1h, *W1h, *Xgh, *Xwh, *Xcath;
    __half *xh0, *xhA, *xhB, *xlasth, *Z1h;
    int *cnt, *rowptr, *colp, *zinit, *cptr, *csrcp;
    cudaGetSymbolAddress((void**)&Xh, g_Xh);
    cudaGetSymbolAddress((void**)&Wgh, g_Wgh);
    cudaGetSymbolAddress((void**)&weighth, g_weighth);
    cudaGetSymbolAddress((void**)&W0h, g_W0h);
    cudaGetSymbolAddress((void**)&Wd1h, g_Wd1h);
    cudaGetSymbolAddress((void**)&W1h, g_W1h);
    cudaGetSymbolAddress((void**)&Xgh, g_Xgh);
    cudaGetSymbolAddress((void**)&Xwh, g_Xwh);
    cudaGetSymbolAddress((void**)&lgcn, g_lgcn);
    cudaGetSymbolAddress((void**)&attpart, g_attpart);
    cudaGetSymbolAddress((void**)&beta, g_beta);
    cudaGetSymbolAddress((void**)&Xcath, g_Xcath);
    cudaGetSymbolAddress((void**)&x0, g_x0);
    cudaGetSymbolAddress((void**)&xlasth, g_xlasth);
    cudaGetSymbolAddress((void**)&xh0, g_xh0);
    cudaGetSymbolAddress((void**)&xhA, g_xhA);
    cudaGetSymbolAddress((void**)&xhB, g_xhB);
    cudaGetSymbolAddress((void**)&Z1h, g_Z1h);
    cudaGetSymbolAddress((void**)&Z2, g_Z2);
    cudaGetSymbolAddress((void**)&ybuf, g_y);
    cudaGetSymbolAddress((void**)&cnt, g_cnt);
    cudaGetSymbolAddress((void**)&rowptr, g_rowptr);
    cudaGetSymbolAddress((void**)&dis, g_dis);
    cudaGetSymbolAddress((void**)&colp, g_col);
    cudaGetSymbolAddress((void**)&valp, g_val);
    cudaGetSymbolAddress((void**)&zinit, g_zinit);
    cudaGetSymbolAddress((void**)&cptr, g_cptr);
    cudaGetSymbolAddress((void**)&csrcp, g_csrc);
    cudaGetSymbolAddress((void**)&cvalp, g_cval);

    int* ccnt = zinit;
    int* cfill = zinit + E_TYPES * N_NODES;
    float* degsum = (float*)(zinit + 2 * E_TYPES * N_NODES);

    cudaMemsetAsync(zinit, 0, 3 * E_TYPES * N_NODES * sizeof(int));

    // 0) fp16 conversions of GEMM operands
    f2h_kernel<<<(N_NODES * W_IN / 4 + 255) / 256, 256>>>(X, Xh, N_NODES * W_IN / 4);
    f2h_kernel<<<(W_IN * W_IN / 4 + 255) / 256, 256>>>(Wg, Wgh, W_IN * W_IN / 4);
    f2h_kernel<<<(W_IN * W_OUT / 4 + 255) / 256, 256>>>(weight, weighth, W_IN * W_OUT / 4);
    f2h_kernel<<<(H0 * W_OUT / 4 + 255) / 256, 256>>>(W0, W0h, H0 * W_OUT / 4);
    f2h_kernel<<<(W_OUT * W_OUT / 4 + 255) / 256, 256>>>(Wd1, Wd1h, W_OUT * W_OUT / 4);
    f2h_kernel<<<(W_OUT * W_OUT / 4 + 255) / 256, 256>>>(W1, W1h, W_OUT * W_OUT / 4);

    // 1) Xg = leaky(X@Wg+bg) [fp16], Xw = leaky(Xg@weight) [fp16]  — HMMA
    hgemm<<<dim3(N_NODES / 128, W_IN / 128), 256>>>(Xh, Wgh, N_NODES, W_IN, W_IN,
                                                    bg, 2, nullptr, Xgh);
    hgemm<<<dim3(N_NODES / 128, 1), 256>>>(Xgh, weighth, N_NODES, W_OUT, W_IN,
                                           nullptr, 2, nullptr, Xwh);
    // 2) sparse structure
    rowcnt_ext<<<N_NODES, 256>>>(A, cnt, dis, ccnt, degsum);
    scan_kernel<<<1, 1024>>>(cnt, rowptr, 0, 0);
    scan_kernel<<<E_TYPES, 1024>>>(ccnt, cptr, N_NODES, N_NODES + 1);
    fill_ext<<<N_NODES, 256>>>(A, rowptr, dis, colp, valp, cptr, cfill, csrcp, cvalp);
    // 3) lgcn (fp16 gather) + attention + concat + x0 (HMMA W0 GEMM)
    lgcn_csc<<<dim3(N_NODES, E_TYPES), 128>>>(Xwh, csrcp, cvalp, cptr, degsum, lgcn);
    att1<<<dim3(ATT_G, E_TYPES), 128>>>(lgcn, attw, attpart);
    att2<<<1, 128>>>(attpart, attb, attq, beta);
    {
        long long total = (long long)N_NODES * H0;
        xcat_kernel<<<(unsigned)((total + 255) / 256), 256>>>(lgcn, X, beta, Xcath);
    }
    hgemm<<<dim3(N_NODES / 128, 1), 256>>>(Xcath, W0h, N_NODES, W_OUT, H0,
                                           b0, 1, x0, xh0);
    // 4) 64 fused GCNII layers (proven gather path; all layers emit fp16)
    const __half* xin = xh0;
    __half* bufs[2] = {xhA, xhB};
    for (int l = 0; l < NUM_LAYERS; l++) {
        float bl = logf(0.5f / (float)(l + 1) + 1.f);
        bool last = (l == NUM_LAYERS - 1);
        __half* xh = last ? xlasth : bufs[l & 1];
        layer_fused4<<<N_NODES / 4, 256>>>(rowptr, colp, valp, xin, x0,
                                           Wconvs + (long long)l * W_OUT * W_OUT, bl, xh);
        xin = xh;
    }
    // 5) head — HMMA: Z1 = leaky(xlast@Wd1+bd1) fp16; Z2 = leaky(Z1@W1+b1) fp32
    hgemm<<<dim3(N_NODES / 128, 1), 256>>>(xlasth, Wd1h, N_NODES, W_OUT, W_OUT,
                                           bd1, 2, nullptr, Z1h);
    hgemm<<<dim3(N_NODES / 128, 1), 256>>>(Z1h, W1h, N_NODES, W_OUT, W_OUT,
                                           b1, 2, Z2, nullptr);
    float* yout;
    bool with_loss;
    if (out_size >= M_TGT * NUM_CLASS + 1) { yout = (float*)d_out + 1; with_loss = true; }
    else if (out_size == M_TGT * NUM_CLASS) { yout = (float*)d_out; with_loss = false; }
    else { yout = ybuf; with_loss = true; }
    out_kernel<<<M_TGT, 128>>>(Z2, target_x, W2, b2, yout);
    if (with_loss) loss_kernel<<<1, 256>>>(yout, target, (float*)d_out);
}

// round 15
// speedup vs baseline: 1.7173x; 1.0887x over previous
#include <cuda_runtime.h>
#include <cuda_fp16.h>
#include <math.h>
#include <stdint.h>

#define N_NODES 4096
#define E_TYPES 5
#define W_IN 512
#define W_OUT 128
#define NUM_CLASS 16
#define M_TGT 1024
#define NUM_LAYERS 64
#define H0 (W_IN + E_TYPES * W_OUT)   // 1152
#define NNZ_CAP 2097152
#define CAPE 262144
#define ATT_G 128

// ---------------- static scratch ----------------
__device__ __half g_Xh[N_NODES * W_IN];
__device__ __half g_Wgh[W_IN * W_IN];
__device__ __half g_weighth[W_IN * W_OUT];
__device__ __half g_W0h[H0 * W_OUT];
__device__ __half g_Wd1h[W_OUT * W_OUT];
__device__ __half g_W1h[W_OUT * W_OUT];
__device__ __half g_Xgh[N_NODES * W_IN];
__device__ __half g_Xwh[N_NODES * W_OUT];
__device__ float g_lgcn[E_TYPES * N_NODES * W_OUT];
__device__ float g_attpart[E_TYPES * ATT_G * W_OUT];
__device__ float g_beta[E_TYPES];
__device__ __half g_Xcath[N_NODES * H0];
__device__ float g_x0[N_NODES * W_OUT];
__device__ float g_hbuf[N_NODES * W_OUT];        // per-layer h (fp32)
__device__ float g_wprime[(size_t)NUM_LAYERS * W_OUT * W_OUT];  // (1-bl)I+bl*Wl fp32
__device__ __half g_xlasth[N_NODES * W_OUT];
__device__ __half g_xh0[N_NODES * W_OUT];
__device__ __half g_xhA[N_NODES * W_OUT];
__device__ __half g_xhB[N_NODES * W_OUT];
__device__ __half g_Z1h[N_NODES * W_OUT];
__device__ float g_Z2[N_NODES * W_OUT];
__device__ float g_y[M_TGT * NUM_CLASS];
__device__ int   g_cnt[N_NODES];
__device__ int   g_rowptr[N_NODES + 1];
__device__ float g_dis[N_NODES];
__device__ int   g_col[NNZ_CAP];
__device__ float g_val[NNZ_CAP];
__device__ int   g_zinit[3 * E_TYPES * N_NODES];
__device__ int   g_cptr[E_TYPES * (N_NODES + 1)];
__device__ int   g_csrc[E_TYPES * CAPE];
__device__ float g_cval[E_TYPES * CAPE];

// ---------------- helpers ----------------
__device__ __forceinline__ float h2_as_f(__half2 h) {
    return __uint_as_float(*(unsigned*)&h);
}
__device__ __forceinline__ uint32_t smem_u32(const void* p) {
    uint32_t a;
    asm("{ .reg .u64 t; cvta.to.shared.u64 t, %1; cvt.u32.u64 %0, t; }" : "=r"(a) : "l"(p));
    return a;
}
__device__ __forceinline__ void cpa16(uint32_t dst, const void* src) {
    asm volatile("cp.async.cg.shared.global [%0], [%1], 16;" :: "r"(dst), "l"(src));
}
__device__ __forceinline__ void ldmx4(uint32_t& r0, uint32_t& r1, uint32_t& r2,
                                      uint32_t& r3, uint32_t addr) {
    asm volatile("ldmatrix.sync.aligned.m8n8.x4.shared.b16 {%0,%1,%2,%3}, [%4];"
                 : "=r"(r0), "=r"(r1), "=r"(r2), "=r"(r3) : "r"(addr));
}
__device__ __forceinline__ void ldmx4t(uint32_t& r0, uint32_t& r1, uint32_t& r2,
                                       uint32_t& r3, uint32_t addr) {
    asm volatile("ldmatrix.sync.aligned.m8n8.x4.trans.shared.b16 {%0,%1,%2,%3}, [%4];"
                 : "=r"(r0), "=r"(r1), "=r"(r2), "=r"(r3) : "r"(addr));
}
__device__ __forceinline__ void mma16816(float* c, uint32_t a0, uint32_t a1, uint32_t a2,
                                         uint32_t a3, uint32_t b0, uint32_t b1) {
    asm volatile(
        "mma.sync.aligned.m16n8k16.row.col.f32.f16.f16.f32 "
        "{%0,%1,%2,%3}, {%4,%5,%6,%7}, {%8,%9}, {%0,%1,%2,%3};"
        : "+f"(c[0]), "+f"(c[1]), "+f"(c[2]), "+f"(c[3])
        : "r"(a0), "r"(a1), "r"(a2), "r"(a3), "r"(b0), "r"(b1));
}

// ---------------- generic fp16 HMMA GEMM with epilogue ----------------
__global__ __launch_bounds__(256, 1) void hgemm(
    const __half* __restrict__ A, const __half* __restrict__ B,
    int M, int N, int K, const float* __restrict__ bias, int act,
    float* __restrict__ Cf, __half* __restrict__ Ch) {
    __shared__ __half As[2][128 * 40];
    __shared__ __half Bs[2][32 * 136];
    int t = threadIdx.x, w = t >> 5, lane = t & 31;
    int m0 = blockIdx.x * 128, n0 = blockIdx.y * 128;
    const __half* Ag = A + (size_t)m0 * K;
    const __half* Bg = B + n0;
    uint32_t asb[2] = {smem_u32(As[0]), smem_u32(As[1])};
    uint32_t bsb[2] = {smem_u32(Bs[0]), smem_u32(Bs[1])};

    auto prefetch = [&](int i, int buf) {
#pragma unroll
        for (int j = 0; j < 2; j++) {
            int cid = t + 256 * j;
            int r = cid >> 2, co = (cid & 3) * 8;
            cpa16(asb[buf] + (r * 40 + co) * 2, Ag + (size_t)r * K + i * 32 + co);
            int rb = cid >> 4, cb = (cid & 15) * 8;
            cpa16(bsb[buf] + (rb * 136 + cb) * 2, Bg + (size_t)(i * 32 + rb) * N + cb);
        }
        asm volatile("cp.async.commit_group;" ::: "memory");
    };
    prefetch(0, 0);
    prefetch(1, 1);

    int wm = w >> 2, wn = w & 3;
    float c[4][4][4];
#pragma unroll
    for (int mi = 0; mi < 4; mi++)
#pragma unroll
        for (int nj = 0; nj < 4; nj++)
#pragma unroll
            for (int q = 0; q < 4; q++) c[mi][nj][q] = 0.f;

    int niter = K / 32;
    for (int i = 0; i < niter; i++) {
        asm volatile("cp.async.wait_group 1;" ::: "memory");
        __syncthreads();
        int buf = i & 1;
        uint32_t ab = asb[buf], bb = bsb[buf];
#pragma unroll
        for (int kk = 0; kk < 2; kk++) {
            uint32_t a[4][4];
#pragma unroll
            for (int mi = 0; mi < 4; mi++) {
                int row = wm * 64 + mi * 16 + (lane & 15);
                int col = kk * 16 + (lane >> 4) * 8;
                ldmx4(a[mi][0], a[mi][1], a[mi][2], a[mi][3], ab + (row * 40 + col) * 2);
            }
            uint32_t b[2][4];
#pragma unroll
            for (int ng = 0; ng < 2; ng++) {
                int row = kk * 16 + (lane & 15);
                int col = wn * 32 + ng * 16 + (lane >> 4) * 8;
                ldmx4t(b[ng][0], b[ng][1], b[ng][2], b[ng][3], bb + (row * 136 + col) * 2);
            }
#pragma unroll
            for (int mi = 0; mi < 4; mi++)
#pragma unroll
                for (int nj = 0; nj < 4; nj++)
                    mma16816(c[mi][nj], a[mi][0], a[mi][1], a[mi][2], a[mi][3],
                             b[nj >> 1][(nj & 1) * 2], b[nj >> 1][(nj & 1) * 2 + 1]);
        }
        __syncthreads();
        if (i + 2 < niter) prefetch(i + 2, buf);
        else asm volatile("cp.async.commit_group;" ::: "memory");
    }

#pragma unroll
    for (int mi = 0; mi < 4; mi++)
#pragma unroll
        for (int nj = 0; nj < 4; nj++) {
            int rl = wm * 64 + mi * 16 + (lane >> 2);
            int cl = wn * 32 + nj * 8 + (lane & 3) * 2;
            float bz0 = bias ? bias[n0 + cl] : 0.f;
            float bz1 = bias ? bias[n0 + cl + 1] : 0.f;
#pragma unroll
            for (int half2i = 0; half2i < 2; half2i++) {
                int row = m0 + rl + half2i * 8;
                float v0 = c[mi][nj][half2i * 2 + 0] + bz0;
                float v1 = c[mi][nj][half2i * 2 + 1] + bz1;
                if (act == 1) { v0 = fmaxf(v0, 0.f); v1 = fmaxf(v1, 0.f); }
                else if (act == 2) {
                    v0 = (v0 >= 0.f) ? v0 : 0.01f * v0;
                    v1 = (v1 >= 0.f) ? v1 : 0.01f * v1;
                }
                if (Cf) *(float2*)(Cf + (size_t)row * N + n0 + cl) = make_float2(v0, v1);
                if (Ch) {
                    __half2 q = __floats2half2_rn(v0, v1);
                    *(unsigned*)(Ch + (size_t)row * N + n0 + cl) = *(unsigned*)&q;
                }
            }
        }
}

// ---------------- sparse structure build ----------------
__global__ void rowcnt_ext(const float* __restrict__ A, int* __restrict__ cnt,
                           float* __restrict__ dis, int* __restrict__ ccnt,
                           float* __restrict__ degsum) {
    int i = blockIdx.x;
    int tid = threadIdx.x;
    int c = 0;
    for (int j = tid; j < N_NODES; j += 256) {
        const float* ap = A + ((long long)i * N_NODES + j) * E_TYPES;
        float a[E_TYPES];
#pragma unroll
        for (int e = 0; e < E_TYPES; e++) a[e] = ap[e];
        bool nz = (j == i);
#pragma unroll
        for (int e = 0; e < E_TYPES; e++) nz |= (a[e] != 0.f);
        c += nz ? 1 : 0;
        if (j != i) {
#pragma unroll
            for (int e = 0; e < E_TYPES; e++) {
                if (a[e] != 0.f) {
                    atomicAdd(&ccnt[e * N_NODES + j], 1);
                    atomicAdd(&degsum[e * N_NODES + j], a[e]);
                }
            }
        }
    }
    __shared__ int red[256];
    red[tid] = c;
    __syncthreads();
    for (int o = 128; o; o >>= 1) {
        if (tid < o) red[tid] += red[tid + o];
        __syncthreads();
    }
    if (tid == 0) {
        cnt[i] = red[0];
        dis[i] = rsqrtf((float)red[0]);
    }
}

__global__ void scan_kernel(const int* __restrict__ cnt_base, int* __restrict__ rp_base,
                            int seg_in, int seg_out) {
    const int* cnt = cnt_base + (long long)blockIdx.x * seg_in;
    int* rowptr = rp_base + (long long)blockIdx.x * seg_out;
    __shared__ int warpsum[32];
    int t = threadIdx.x;
    int v[4], s = 0;
#pragma unroll
    for (int j = 0; j < 4; j++) { v[j] = cnt[t * 4 + j]; s += v[j]; }
    int lane = t & 31, warp = t >> 5;
    int x = s;
#pragma unroll
    for (int o = 1; o < 32; o <<= 1) {
        int y = __shfl_up_sync(0xffffffffu, x, o);
        if (lane >= o) x += y;
    }
    if (lane == 31) warpsum[warp] = x;
    __syncthreads();
    if (warp == 0) {
        int w = warpsum[lane];
#pragma unroll
        for (int o = 1; o < 32; o <<= 1) {
            int y = __shfl_up_sync(0xffffffffu, w, o);
            if (lane >= o) w += y;
        }
        warpsum[lane] = w;
    }
    __syncthreads();
    int excl = x - s + (warp ? warpsum[warp - 1] : 0);
    int run = excl;
    if (t == 0) rowptr[0] = 0;
#pragma unroll
    for (int j = 0; j < 4; j++) { run += v[j]; rowptr[t * 4 + j + 1] = run; }
}

__global__ void fill_ext(const float* __restrict__ A, const int* __restrict__ rowptr,
                         const float* __restrict__ dis, int* __restrict__ col,
                         float* __restrict__ val, const int* __restrict__ cptr,
                         int* __restrict__ cfill, int* __restrict__ csrc,
                         float* __restrict__ cval) {
    int i = blockIdx.x;
    float di = dis[i];
    __shared__ int warpCnt[8];
    __shared__ int blockBase;
    if (threadIdx.x == 0) blockBase = rowptr[i];
    __syncthreads();
    for (int j0 = 0; j0 < N_NODES; j0 += 256) {
        int j = j0 + threadIdx.x;
        const float* ap = A + ((long long)i * N_NODES + j) * E_TYPES;
        float a[E_TYPES];
#pragma unroll
        for (int e = 0; e < E_TYPES; e++) a[e] = ap[e];
        bool nz = (j == i);
#pragma unroll
        for (int e = 0; e < E_TYPES; e++) nz |= (a[e] != 0.f);
        if (j != i) {
#pragma unroll
            for (int e = 0; e < E_TYPES; e++) {
                if (a[e] != 0.f) {
                    int slot = atomicAdd(&cfill[e * N_NODES + j], 1);
                    int pos = cptr[e * (N_NODES + 1) + j] + slot;
                    csrc[e * CAPE + pos] = i;
                    cval[e * CAPE + pos] = a[e];
                }
            }
        }
        unsigned mask = __ballot_sync(0xffffffffu, nz);
        int warp = threadIdx.x >> 5, lane = threadIdx.x & 31;
        if (lane == 0) warpCnt[warp] = __popc(mask);
        __syncthreads();
        int woff = 0;
        for (int w = 0; w < warp; w++) woff += warpCnt[w];
        int total = 0;
        for (int w = 0; w < 8; w++) total += warpCnt[w];
        if (nz) {
            int pos = blockBase + woff + __popc(mask & ((1u << lane) - 1));
            col[pos] = j;
            val[pos] = di * dis[j];
        }
        __syncthreads();
        if (threadIdx.x == 0) blockBase += total;
        __syncthreads();
    }
}

// ---------------- lgcn via per-e CSC gather (fp16 source) ----------------
__global__ void lgcn_csc(const __half* __restrict__ Xwh, const int* __restrict__ csrc,
                         const float* __restrict__ cval, const int* __restrict__ cptr,
                         const float* __restrict__ degsum, float* __restrict__ lgcn) {
    int n = blockIdx.x, e = blockIdx.y, d = threadIdx.x;
    int s = cptr[e * (N_NODES + 1) + n], en = cptr[e * (N_NODES + 1) + n + 1];
    const int* cs = csrc + (long long)e * CAPE;
    const float* cv = cval + (long long)e * CAPE;
    float acc = __half2float(Xwh[(long long)n * W_OUT + d]);
    for (int k = s; k < en; k++)
        acc += cv[k] * __half2float(Xwh[(long long)cs[k] * W_OUT + d]);
    float dv = 1.f / (1.f + degsum[e * N_NODES + n]);
    lgcn[((long long)e * N_NODES + n) * W_OUT + d] = fmaxf(acc * dv, 0.f);
}

__global__ void att1(const float* __restrict__ lgcn, const float* __restrict__ attw,
                     float* __restrict__ attpart) {
    int g = blockIdx.x, e = blockIdx.y, d = threadIdx.x;
    float s = 0.f;
    int n0 = g * (N_NODES / ATT_G);
    for (int n = n0; n < n0 + N_NODES / ATT_G; n++)
        s += attw[n] * lgcn[((long long)e * N_NODES + n) * W_OUT + d];
    attpart[(e * ATT_G + g) * W_OUT + d] = s;
}

__global__ void att2(const float* __restrict__ attpart, const float* __restrict__ attb,
                     const float* __restrict__ attq, float* __restrict__ beta) {
    __shared__ float red[128];
    __shared__ float w[E_TYPES];
    int d = threadIdx.x;
    for (int e = 0; e < E_TYPES; e++) {
        float tot = 0.f;
#pragma unroll 8
        for (int g = 0; g < ATT_G; g++) tot += attpart[(e * ATT_G + g) * W_OUT + d];
        red[d] = tanhf(tot + attb[d]) * attq[d];
        __syncthreads();
        for (int o = 64; o; o >>= 1) {
            if (d < o) red[d] += red[d + o];
            __syncthreads();
        }
        if (d == 0) w[e] = red[0];
        __syncthreads();
    }
    if (d == 0) {
        float mx = w[0];
        for (int e = 1; e < E_TYPES; e++) mx = fmaxf(mx, w[e]);
        float ex[E_TYPES], s = 0.f;
        for (int e = 0; e < E_TYPES; e++) { ex[e] = expf(w[e] - mx); s += ex[e]; }
        for (int e = 0; e < E_TYPES; e++) beta[e] = (float)E_TYPES * ex[e] / s;
    }
}

__global__ void xcat_kernel(const float* __restrict__ lgcn, const float* __restrict__ X,
                            const float* __restrict__ beta, __half* __restrict__ Xcat) {
    long long idx = (long long)blockIdx.x * 256 + threadIdx.x;
    long long total = (long long)N_NODES * H0;
    if (idx >= total) return;
    int n = (int)(idx / H0), c = (int)(idx % H0);
    float v;
    if (c < E_TYPES * W_OUT) {
        int e = c >> 7, d = c & 127;
        v = beta[e] * lgcn[((long long)e * N_NODES + n) * W_OUT + d];
    } else {
        v = X[(long long)n * W_IN + (c - E_TYPES * W_OUT)];
    }
    Xcat[idx] = __float2half(v);
}

// ---------------- fp32 -> fp16 convert ----------------
__global__ void f2h_kernel(const float* __restrict__ src, __half* __restrict__ dst, int n4) {
    int i = blockIdx.x * 256 + threadIdx.x;
    if (i >= n4) return;
    float4 v = ((const float4*)src)[i];
    __half2 h0 = __floats2half2_rn(v.x, v.y);
    __half2 h1 = __floats2half2_rn(v.z, v.w);
    ((float2*)dst)[i] = make_float2(h2_as_f(h0), h2_as_f(h1));
}

// ---------------- W' prep (fp32): (1-bl)I + bl*Wl ----------------
__global__ void wprime_prep(const float* __restrict__ W, float* __restrict__ wp) {
    int l = blockIdx.x;
    float bl = logf(0.5f / (float)(l + 1) + 1.f);
    float omb = 1.f - bl;
    const float* Wl = W + (size_t)l * W_OUT * W_OUT;
    float* o = wp + (size_t)l * W_OUT * W_OUT;
    for (int i = threadIdx.x; i < W_OUT * W_OUT; i += 256) {
        int k = i >> 7, n = i & 127;
        o[i] = bl * Wl[i] + (k == n ? omb : 0.f);
    }
}

// ---------------- gather: h = 0.9*A_hat@x + 0.1*x0 (fp32 out) ----------------
// 4 rows/block, 2 warps/row (proven decomposition), no dense phase.
__global__ __launch_bounds__(256) void gather4(
    const int* __restrict__ rowptr, const int* __restrict__ colp,
    const float* __restrict__ valp, const __half* __restrict__ xh,
    const float* __restrict__ x0, float* __restrict__ h_out) {
    __shared__ float ps[4][128];
    int t = threadIdx.x;
    int warp = t >> 5, lane = t & 31;
    int rloc = warp >> 1, half = warp & 1;
    int row = blockIdx.x * 4 + rloc;
    int ks = rowptr[row], ke = rowptr[row + 1];
    float a0 = 0.f, a1 = 0.f, a2 = 0.f, a3 = 0.f;
    for (int k0 = ks + half * 32; k0 < ke; k0 += 64) {
        int cnt = min(32, ke - k0);
        int cR = 0; float vR = 0.f;
        if (lane < cnt) { cR = colp[k0 + lane]; vR = valp[k0 + lane]; }
#pragma unroll 4
        for (int kk = 0; kk < cnt; kk++) {
            int c = __shfl_sync(0xffffffffu, cR, kk);
            float v = __shfl_sync(0xffffffffu, vR, kk);
            float2 raw = ((const float2*)(xh + (long long)c * W_OUT))[lane];
            __half2 p0 = *(__half2*)&raw.x;
            __half2 p1 = *(__half2*)&raw.y;
            float2 f0 = __half22float2(p0);
            float2 f1 = __half22float2(p1);
            a0 += v * f0.x; a1 += v * f0.y; a2 += v * f1.x; a3 += v * f1.y;
        }
    }
    if (half) {
        ps[rloc][lane * 4 + 0] = a0;
        ps[rloc][lane * 4 + 1] = a1;
        ps[rloc][lane * 4 + 2] = a2;
        ps[rloc][lane * 4 + 3] = a3;
    }
    __syncthreads();
    if (!half) {
        const float4 xv = ((const float4*)(x0 + (long long)row * W_OUT))[lane];
        float4 o;
        o.x = 0.9f * (a0 + ps[rloc][lane * 4 + 0]) + 0.1f * xv.x;
        o.y = 0.9f * (a1 + ps[rloc][lane * 4 + 1]) + 0.1f * xv.y;
        o.z = 0.9f * (a2 + ps[rloc][lane * 4 + 2]) + 0.1f * xv.z;
        o.w = 0.9f * (a3 + ps[rloc][lane * 4 + 3]) + 0.1f * xv.w;
        *(float4*)(h_out + (long long)row * W_OUT + lane * 4) = o;
    }
}

// ---------------- combine: out_fp16 = relu(h @ W') (proven fp32 path) ----------------
// grid 128 (32-row tiles), 256 thr; warp ty rows ty*4.., lane cols tx*4..
__global__ __launch_bounds__(256) void combine32(
    const float* __restrict__ h, const float* __restrict__ wp,
    __half* __restrict__ xh_out) {
    __shared__ float hs[32 * 132];
    __shared__ float Ws[32 * 128];
    int t = threadIdx.x;
    int tx = t & 31, ty = t >> 5;
    int m0 = blockIdx.x * 32;
#pragma unroll
    for (int j = 0; j < 4; j++) {
        int e4 = t + 256 * j;                  // 1024 float4 = 32x128
        int r = e4 >> 5, c4 = (e4 & 31) * 4;
        *(float4*)(hs + r * 132 + c4) =
            *(const float4*)(h + (size_t)(m0 + r) * W_OUT + c4);
    }
    float acc[4][4];
#pragma unroll
    for (int i = 0; i < 4; i++)
#pragma unroll
        for (int q = 0; q < 4; q++) acc[i][q] = 0.f;
    for (int k0 = 0; k0 < 128; k0 += 32) {
        __syncthreads();                       // first iter also publishes hs
#pragma unroll
        for (int j = 0; j < 4; j++) {
            int idx = t + 256 * j;
            int r = idx >> 5, c4 = (idx & 31) * 4;
            *(float4*)(Ws + r * 128 + c4) = *(const float4*)(wp + (k0 + r) * W_OUT + c4);
        }
        __syncthreads();
#pragma unroll
        for (int kk = 0; kk < 32; kk++) {
            float4 b = *(const float4*)(Ws + kk * 128 + tx * 4);
#pragma unroll
            for (int i = 0; i < 4; i++) {
                float a = hs[(ty * 4 + i) * 132 + k0 + kk];
                acc[i][0] += a * b.x; acc[i][1] += a * b.y;
                acc[i][2] += a * b.z; acc[i][3] += a * b.w;
            }
        }
    }
#pragma unroll
    for (int i = 0; i < 4; i++) {
        int row = m0 + ty * 4 + i;
        float v0 = fmaxf(acc[i][0], 0.f), v1 = fmaxf(acc[i][1], 0.f);
        float v2 = fmaxf(acc[i][2], 0.f), v3 = fmaxf(acc[i][3], 0.f);
        __half2 q0 = __floats2half2_rn(v0, v1);
        __half2 q1 = __floats2half2_rn(v2, v3);
        *(float2*)(xh_out + (size_t)row * W_OUT + tx * 4) =
            make_float2(h2_as_f(q0), h2_as_f(q1));
    }
}

// ---------------- head ----------------
__global__ void out_kernel(const float* __restrict__ Z, const int* __restrict__ tx,
                           const float* __restrict__ W2, const float* __restrict__ b2,
                           float* __restrict__ y) {
    int r = blockIdx.x;
    int t = threadIdx.x;
    __shared__ float z[W_OUT];
    z[t] = Z[(long long)tx[r] * W_OUT + t];
    __syncthreads();
    if (t < NUM_CLASS) {
        float s = b2[t];
        for (int k = 0; k < W_OUT; k++) s += z[k] * W2[k * NUM_CLASS + t];
        y[r * NUM_CLASS + t] = s;
    }
}

__global__ void loss_kernel(const float* __restrict__ y, const int* __restrict__ target,
                            float* __restrict__ out) {
    __shared__ float red[256];
    int tid = threadIdx.x;
    float part = 0.f;
    for (int r = tid; r < M_TGT; r += 256) {
        const float* yr = y + r * NUM_CLASS;
        float mx = yr[0];
#pragma unroll
        for (int c = 1; c < NUM_CLASS; c++) mx = fmaxf(mx, yr[c]);
        float se = 0.f;
#pragma unroll
        for (int c = 0; c < NUM_CLASS; c++) se += expf(yr[c] - mx);
        float lse = mx + logf(se);
        part += lse - yr[target[r]];
    }
    red[tid] = part;
    __syncthreads();
    for (int o = 128; o; o >>= 1) {
        if (tid < o) red[tid] += red[tid + o];
        __syncthreads();
    }
    if (tid == 0) out[0] = red[0] / (float)M_TGT;
}

// ---------------- launch ----------------
extern "C" void kernel_launch(void* const* d_in, const int* in_sizes, int n_in,
                              void* d_out, int out_size) {
    const float* A        = (const float*)d_in[0];
    const float* X        = (const float*)d_in[1];
    const int*   target_x = (const int*)d_in[2];
    const int*   target   = (const int*)d_in[3];
    const float* weight   = (const float*)d_in[4];
    const float* attw     = (const float*)d_in[5];
    const float* attb     = (const float*)d_in[6];
    const float* attq     = (const float*)d_in[7];
    const float* Wg       = (const float*)d_in[8];
    const float* bg       = (const float*)d_in[9];
    const float* W0       = (const float*)d_in[10];
    const float* b0       = (const float*)d_in[11];
    const float* Wconvs   = (const float*)d_in[12];
    const float* Wd1      = (const float*)d_in[13];
    const float* bd1      = (const float*)d_in[14];
    const float* W1       = (const float*)d_in[15];
    const float* b1       = (const float*)d_in[16];
    const float* W2       = (const float*)d_in[17];
    const float* b2       = (const float*)d_in[18];

    float *lgcn, *attpart, *beta, *x0, *Z2, *ybuf, *hbuf, *wp;
    float *dis, *valp, *cvalp;
    __half *Xh, *Wgh, *weighth, *W0h, *Wd1h, *W1h, *Xgh, *Xwh, *Xcath;
    __half *xh0, *xhA, *xhB, *xlasth, *Z1h;
    int *cnt, *rowptr, *colp, *zinit, *cptr, *csrcp;
    cudaGetSymbolAddress((void**)&Xh, g_Xh);
    cudaGetSymbolAddress((void**)&Wgh, g_Wgh);
    cudaGetSymbolAddress((void**)&weighth, g_weighth);
    cudaGetSymbolAddress((void**)&W0h, g_W0h);
    cudaGetSymbolAddress((void**)&Wd1h, g_Wd1h);
    cudaGetSymbolAddress((void**)&W1h, g_W1h);
    cudaGetSymbolAddress((void**)&Xgh, g_Xgh);
    cudaGetSymbolAddress((void**)&Xwh, g_Xwh);
    cudaGetSymbolAddress((void**)&lgcn, g_lgcn);
    cudaGetSymbolAddress((void**)&attpart, g_attpart);
    cudaGetSymbolAddress((void**)&beta, g_beta);
    cudaGetSymbolAddress((void**)&Xcath, g_Xcath);
    cudaGetSymbolAddress((void**)&x0, g_x0);
    cudaGetSymbolAddress((void**)&hbuf, g_hbuf);
    cudaGetSymbolAddress((void**)&wp, g_wprime);
    cudaGetSymbolAddress((void**)&xlasth, g_xlasth);
    cudaGetSymbolAddress((void**)&xh0, g_xh0);
    cudaGetSymbolAddress((void**)&xhA, g_xhA);
    cudaGetSymbolAddress((void**)&xhB, g_xhB);
    cudaGetSymbolAddress((void**)&Z1h, g_Z1h);
    cudaGetSymbolAddress((void**)&Z2, g_Z2);
    cudaGetSymbolAddress((void**)&ybuf, g_y);
    cudaGetSymbolAddress((void**)&cnt, g_cnt);
    cudaGetSymbolAddress((void**)&rowptr, g_rowptr);
    cudaGetSymbolAddress((void**)&dis, g_dis);
    cudaGetSymbolAddress((void**)&colp, g_col);
    cudaGetSymbolAddress((void**)&valp, g_val);
    cudaGetSymbolAddress((void**)&zinit, g_zinit);
    cudaGetSymbolAddress((void**)&cptr, g_cptr);
    cudaGetSymbolAddress((void**)&csrcp, g_csrc);
    cudaGetSymbolAddress((void**)&cvalp, g_cval);

    int* ccnt = zinit;
    int* cfill = zinit + E_TYPES * N_NODES;
    float* degsum = (float*)(zinit + 2 * E_TYPES * N_NODES);

    cudaMemsetAsync(zinit, 0, 3 * E_TYPES * N_NODES * sizeof(int));

    // 0) fp16 conversions of GEMM operands
    f2h_kernel<<<(N_NODES * W_IN / 4 + 255) / 256, 256>>>(X, Xh, N_NODES * W_IN / 4);
    f2h_kernel<<<(W_IN * W_IN / 4 + 255) / 256, 256>>>(Wg, Wgh, W_IN * W_IN / 4);
    f2h_kernel<<<(W_IN * W_OUT / 4 + 255) / 256, 256>>>(weight, weighth, W_IN * W_OUT / 4);
    f2h_kernel<<<(H0 * W_OUT / 4 + 255) / 256, 256>>>(W0, W0h, H0 * W_OUT / 4);
    f2h_kernel<<<(W_OUT * W_OUT / 4 + 255) / 256, 256>>>(Wd1, Wd1h, W_OUT * W_OUT / 4);
    f2h_kernel<<<(W_OUT * W_OUT / 4 + 255) / 256, 256>>>(W1, W1h, W_OUT * W_OUT / 4);

    // 1) Xg = leaky(X@Wg+bg) [fp16], Xw = leaky(Xg@weight) [fp16]  — HMMA
    hgemm<<<dim3(N_NODES / 128, W_IN / 128), 256>>>(Xh, Wgh, N_NODES, W_IN, W_IN,
                                                    bg, 2, nullptr, Xgh);
    hgemm<<<dim3(N_NODES / 128, 1), 256>>>(Xgh, weighth, N_NODES, W_OUT, W_IN,
                                           nullptr, 2, nullptr, Xwh);
    // 2) sparse structure + W' prep
    rowcnt_ext<<<N_NODES, 256>>>(A, cnt, dis, ccnt, degsum);
    scan_kernel<<<1, 1024>>>(cnt, rowptr, 0, 0);
    scan_kernel<<<E_TYPES, 1024>>>(ccnt, cptr, N_NODES, N_NODES + 1);
    fill_ext<<<N_NODES, 256>>>(A, rowptr, dis, colp, valp, cptr, cfill, csrcp, cvalp);
    wprime_prep<<<NUM_LAYERS, 256>>>(Wconvs, wp);
    // 3) lgcn (fp16 gather) + attention + concat + x0 (HMMA W0 GEMM)
    lgcn_csc<<<dim3(N_NODES, E_TYPES), 128>>>(Xwh, csrcp, cvalp, cptr, degsum, lgcn);
    att1<<<dim3(ATT_G, E_TYPES), 128>>>(lgcn, attw, attpart);
    att2<<<1, 128>>>(attpart, attb, attq, beta);
    {
        long long total = (long long)N_NODES * H0;
        xcat_kernel<<<(unsigned)((total + 255) / 256), 256>>>(lgcn, X, beta, Xcath);
    }
    hgemm<<<dim3(N_NODES / 128, 1), 256>>>(Xcath, W0h, N_NODES, W_OUT, H0,
                                           b0, 1, x0, xh0);
    // 4) 64 GCNII layers: gather (BW-bound) + combine (fp32 W' GEMM)
    const __half* xin = xh0;
    __half* bufs[2] = {xhA, xhB};
    for (int l = 0; l < NUM_LAYERS; l++) {
        bool last = (l == NUM_LAYERS - 1);
        __half* xhout = last ? xlasth : bufs[l & 1];
        gather4<<<N_NODES / 4, 256>>>(rowptr, colp, valp, xin, x0, hbuf);
        combine32<<<N_NODES / 32, 256>>>(hbuf, wp + (size_t)l * W_OUT * W_OUT, xhout);
        xin = xhout;
    }
    // 5) head — HMMA
    hgemm<<<dim3(N_NODES / 128, 1), 256>>>(xlasth, Wd1h, N_NODES, W_OUT, W_OUT,
                                           bd1, 2, nullptr, Z1h);
    hgemm<<<dim3(N_NODES / 128, 1), 256>>>(Z1h, W1h, N_NODES, W_OUT, W_OUT,
                                           b1, 2, Z2, nullptr);
    float* yout;
    bool with_loss;
    if (out_size >= M_TGT * NUM_CLASS + 1) { yout = (float*)d_out + 1; with_loss = true; }
    else if (out_size == M_TGT * NUM_CLASS) { yout = (float*)d_out; with_loss = false; }
    else { yout = ybuf; with_loss = true; }
    out_kernel<<<M_TGT, 128>>>(Z2, target_x, W2, b2, yout);
    if (with_loss) loss_kernel<<<1, 256>>>(yout, target, (float*)d_out);
}

// round 16
// speedup vs baseline: 1.8403x; 1.0716x over previous
#include <cuda_runtime.h>
#include <cuda_fp16.h>
#include <math.h>
#include <stdint.h>

#define N_NODES 4096
#define E_TYPES 5
#define W_IN 512
#define W_OUT 128
#define NUM_CLASS 16
#define M_TGT 1024
#define NUM_LAYERS 64
#define H0 (W_IN + E_TYPES * W_OUT)   // 1152
#define NNZ_CAP 2097152
#define ATT_G 128
#define CAP_R 384
#define CAP_C 128

// ---------------- static scratch ----------------
__device__ __half g_Xh[N_NODES * W_IN];
__device__ __half g_Wgh[W_IN * W_IN];
__device__ __half g_weighth[W_IN * W_OUT];
__device__ __half g_W0h[H0 * W_OUT];
__device__ __half g_Wd1h[W_OUT * W_OUT];
__device__ __half g_W1h[W_OUT * W_OUT];
__device__ __half g_Xgh[N_NODES * W_IN];
__device__ __half g_Xwh[N_NODES * W_OUT];
__device__ float g_lgcn[E_TYPES * N_NODES * W_OUT];
__device__ float g_attpart[E_TYPES * ATT_G * W_OUT];
__device__ float g_beta[E_TYPES];
__device__ __half g_Xcath[N_NODES * H0];
__device__ float g_x0[N_NODES * W_OUT];
__device__ float g_hbuf[N_NODES * W_OUT];
__device__ float g_wprime[(size_t)NUM_LAYERS * W_OUT * W_OUT];
__device__ __half g_xlasth[N_NODES * W_OUT];
__device__ __half g_xh0[N_NODES * W_OUT];
__device__ __half g_xhA[N_NODES * W_OUT];
__device__ __half g_xhB[N_NODES * W_OUT];
__device__ __half g_Z1h[N_NODES * W_OUT];
__device__ float g_Z2[N_NODES * W_OUT];
__device__ float g_y[M_TGT * NUM_CLASS];
__device__ int   g_cnt[N_NODES];
__device__ int   g_rowptr[N_NODES + 1];
__device__ float g_dis[N_NODES];
__device__ float2 g_cv[NNZ_CAP];                     // interleaved (col_bits, val)
__device__ int   g_rcol[(size_t)N_NODES * CAP_R];    // padded CSR cols
__device__ int   g_csrc[(size_t)E_TYPES * N_NODES * CAP_C];   // padded CSC src
__device__ float g_cvalp[(size_t)E_TYPES * N_NODES * CAP_C];  // padded CSC val
__device__ int   g_zinit[2 * E_TYPES * N_NODES];     // ccnt | degsum(float)

// ---------------- helpers ----------------
__device__ __forceinline__ float h2_as_f(__half2 h) {
    return __uint_as_float(*(unsigned*)&h);
}
__device__ __forceinline__ uint32_t smem_u32(const void* p) {
    uint32_t a;
    asm("{ .reg .u64 t; cvta.to.shared.u64 t, %1; cvt.u32.u64 %0, t; }" : "=r"(a) : "l"(p));
    return a;
}
__device__ __forceinline__ void cpa16(uint32_t dst, const void* src) {
    asm volatile("cp.async.cg.shared.global [%0], [%1], 16;" :: "r"(dst), "l"(src));
}
__device__ __forceinline__ void ldmx4(uint32_t& r0, uint32_t& r1, uint32_t& r2,
                                      uint32_t& r3, uint32_t addr) {
    asm volatile("ldmatrix.sync.aligned.m8n8.x4.shared.b16 {%0,%1,%2,%3}, [%4];"
                 : "=r"(r0), "=r"(r1), "=r"(r2), "=r"(r3) : "r"(addr));
}
__device__ __forceinline__ void ldmx4t(uint32_t& r0, uint32_t& r1, uint32_t& r2,
                                       uint32_t& r3, uint32_t addr) {
    asm volatile("ldmatrix.sync.aligned.m8n8.x4.trans.shared.b16 {%0,%1,%2,%3}, [%4];"
                 : "=r"(r0), "=r"(r1), "=r"(r2), "=r"(r3) : "r"(addr));
}
__device__ __forceinline__ void mma16816(float* c, uint32_t a0, uint32_t a1, uint32_t a2,
                                         uint32_t a3, uint32_t b0, uint32_t b1) {
    asm volatile(
        "mma.sync.aligned.m16n8k16.row.col.f32.f16.f16.f32 "
        "{%0,%1,%2,%3}, {%4,%5,%6,%7}, {%8,%9}, {%0,%1,%2,%3};"
        : "+f"(c[0]), "+f"(c[1]), "+f"(c[2]), "+f"(c[3])
        : "r"(a0), "r"(a1), "r"(a2), "r"(a3), "r"(b0), "r"(b1));
}

// ---------------- generic fp16 HMMA GEMM with epilogue ----------------
__global__ __launch_bounds__(256, 1) void hgemm(
    const __half* __restrict__ A, const __half* __restrict__ B,
    int M, int N, int K, const float* __restrict__ bias, int act,
    float* __restrict__ Cf, __half* __restrict__ Ch) {
    __shared__ __half As[2][128 * 40];
    __shared__ __half Bs[2][32 * 136];
    int t = threadIdx.x, w = t >> 5, lane = t & 31;
    int m0 = blockIdx.x * 128, n0 = blockIdx.y * 128;
    const __half* Ag = A + (size_t)m0 * K;
    const __half* Bg = B + n0;
    uint32_t asb[2] = {smem_u32(As[0]), smem_u32(As[1])};
    uint32_t bsb[2] = {smem_u32(Bs[0]), smem_u32(Bs[1])};

    auto prefetch = [&](int i, int buf) {
#pragma unroll
        for (int j = 0; j < 2; j++) {
            int cid = t + 256 * j;
            int r = cid >> 2, co = (cid & 3) * 8;
            cpa16(asb[buf] + (r * 40 + co) * 2, Ag + (size_t)r * K + i * 32 + co);
            int rb = cid >> 4, cb = (cid & 15) * 8;
            cpa16(bsb[buf] + (rb * 136 + cb) * 2, Bg + (size_t)(i * 32 + rb) * N + cb);
        }
        asm volatile("cp.async.commit_group;" ::: "memory");
    };
    prefetch(0, 0);
    prefetch(1, 1);

    int wm = w >> 2, wn = w & 3;
    float c[4][4][4];
#pragma unroll
    for (int mi = 0; mi < 4; mi++)
#pragma unroll
        for (int nj = 0; nj < 4; nj++)
#pragma unroll
            for (int q = 0; q < 4; q++) c[mi][nj][q] = 0.f;

    int niter = K / 32;
    for (int i = 0; i < niter; i++) {
        asm volatile("cp.async.wait_group 1;" ::: "memory");
        __syncthreads();
        int buf = i & 1;
        uint32_t ab = asb[buf], bb = bsb[buf];
#pragma unroll
        for (int kk = 0; kk < 2; kk++) {
            uint32_t a[4][4];
#pragma unroll
            for (int mi = 0; mi < 4; mi++) {
                int row = wm * 64 + mi * 16 + (lane & 15);
                int col = kk * 16 + (lane >> 4) * 8;
                ldmx4(a[mi][0], a[mi][1], a[mi][2], a[mi][3], ab + (row * 40 + col) * 2);
            }
            uint32_t b[2][4];
#pragma unroll
            for (int ng = 0; ng < 2; ng++) {
                int row = kk * 16 + (lane & 15);
                int col = wn * 32 + ng * 16 + (lane >> 4) * 8;
                ldmx4t(b[ng][0], b[ng][1], b[ng][2], b[ng][3], bb + (row * 136 + col) * 2);
            }
#pragma unroll
            for (int mi = 0; mi < 4; mi++)
#pragma unroll
                for (int nj = 0; nj < 4; nj++)
                    mma16816(c[mi][nj], a[mi][0], a[mi][1], a[mi][2], a[mi][3],
                             b[nj >> 1][(nj & 1) * 2], b[nj >> 1][(nj & 1) * 2 + 1]);
        }
        __syncthreads();
        if (i + 2 < niter) prefetch(i + 2, buf);
        else asm volatile("cp.async.commit_group;" ::: "memory");
    }

#pragma unroll
    for (int mi = 0; mi < 4; mi++)
#pragma unroll
        for (int nj = 0; nj < 4; nj++) {
            int rl = wm * 64 + mi * 16 + (lane >> 2);
            int cl = wn * 32 + nj * 8 + (lane & 3) * 2;
            float bz0 = bias ? bias[n0 + cl] : 0.f;
            float bz1 = bias ? bias[n0 + cl + 1] : 0.f;
#pragma unroll
            for (int half2i = 0; half2i < 2; half2i++) {
                int row = m0 + rl + half2i * 8;
                float v0 = c[mi][nj][half2i * 2 + 0] + bz0;
                float v1 = c[mi][nj][half2i * 2 + 1] + bz1;
                if (act == 1) { v0 = fmaxf(v0, 0.f); v1 = fmaxf(v1, 0.f); }
                else if (act == 2) {
                    v0 = (v0 >= 0.f) ? v0 : 0.01f * v0;
                    v1 = (v1 >= 0.f) ? v1 : 0.01f * v1;
                }
                if (Cf) *(float2*)(Cf + (size_t)row * N + n0 + cl) = make_float2(v0, v1);
                if (Ch) {
                    __half2 q = __floats2half2_rn(v0, v1);
                    *(unsigned*)(Ch + (size_t)row * N + n0 + cl) = *(unsigned*)&q;
                }
            }
        }
}

// ---------------- single-pass A scan: counts + padded CSR/CSC stores ----------------
__global__ void build_all(const float* __restrict__ A, int* __restrict__ cnt,
                          float* __restrict__ dis, int* __restrict__ ccnt,
                          float* __restrict__ degsum, int* __restrict__ rcol,
                          int* __restrict__ csrc, float* __restrict__ cvalp) {
    int i = blockIdx.x;
    int tid = threadIdx.x;
    __shared__ int rcount;
    if (tid == 0) rcount = 0;
    __syncthreads();
    int* rc = rcol + (size_t)i * CAP_R;
    for (int j = tid; j < N_NODES; j += 256) {
        const float* ap = A + ((long long)i * N_NODES + j) * E_TYPES;
        float a[E_TYPES];
#pragma unroll
        for (int e = 0; e < E_TYPES; e++) a[e] = ap[e];
        bool nz = (j == i);
#pragma unroll
        for (int e = 0; e < E_TYPES; e++) nz |= (a[e] != 0.f);
        if (nz) {
            int slot = atomicAdd(&rcount, 1);
            if (slot < CAP_R) rc[slot] = j;
        }
        if (j != i) {
#pragma unroll
            for (int e = 0; e < E_TYPES; e++) {
                if (a[e] != 0.f) {
                    int cs = atomicAdd(&ccnt[e * N_NODES + j], 1);
                    if (cs < CAP_C) {
                        size_t p = (size_t)(e * N_NODES + j) * CAP_C + cs;
                        csrc[p] = i;
                        cvalp[p] = a[e];
                    }
                    atomicAdd(&degsum[e * N_NODES + j], a[e]);
                }
            }
        }
    }
    __syncthreads();
    if (tid == 0) {
        int c = min(rcount, CAP_R);
        cnt[i] = c;
        dis[i] = rsqrtf((float)rcount);
    }
}

__global__ void scan_kernel(const int* __restrict__ cnt, int* __restrict__ rowptr) {
    __shared__ int warpsum[32];
    int t = threadIdx.x;                   // 1024, 4 elems each
    int v[4], s = 0;
#pragma unroll
    for (int j = 0; j < 4; j++) { v[j] = cnt[t * 4 + j]; s += v[j]; }
    int lane = t & 31, warp = t >> 5;
    int x = s;
#pragma unroll
    for (int o = 1; o < 32; o <<= 1) {
        int y = __shfl_up_sync(0xffffffffu, x, o);
        if (lane >= o) x += y;
    }
    if (lane == 31) warpsum[warp] = x;
    __syncthreads();
    if (warp == 0) {
        int w = warpsum[lane];
#pragma unroll
        for (int o = 1; o < 32; o <<= 1) {
            int y = __shfl_up_sync(0xffffffffu, w, o);
            if (lane >= o) w += y;
        }
        warpsum[lane] = w;
    }
    __syncthreads();
    int excl = x - s + (warp ? warpsum[warp - 1] : 0);
    int run = excl;
    if (t == 0) rowptr[0] = 0;
#pragma unroll
    for (int j = 0; j < 4; j++) { run += v[j]; rowptr[t * 4 + j + 1] = run; }
}

// ---------------- compact CSR into interleaved (col,val) ----------------
__global__ void compact_csr(const int* __restrict__ cnt, const int* __restrict__ rowptr,
                            const int* __restrict__ rcol, const float* __restrict__ dis,
                            float2* __restrict__ cv) {
    int i = blockIdx.x;
    int n = cnt[i];
    int base = rowptr[i];
    float di = dis[i];
    const int* rc = rcol + (size_t)i * CAP_R;
    for (int s = threadIdx.x; s < n; s += 256) {
        int j = rc[s];
        cv[base + s] = make_float2(__int_as_float(j), di * dis[j]);
    }
}

// ---------------- lgcn from padded CSC (fp16 feature source) ----------------
__global__ void lgcn_pad(const __half* __restrict__ Xwh, const int* __restrict__ csrc,
                         const float* __restrict__ cvalp, const int* __restrict__ ccnt,
                         const float* __restrict__ degsum, float* __restrict__ lgcn) {
    int n = blockIdx.x, e = blockIdx.y, d = threadIdx.x;
    int cntv = min(ccnt[e * N_NODES + n], CAP_C);
    size_t base = (size_t)(e * N_NODES + n) * CAP_C;
    float acc = __half2float(Xwh[(long long)n * W_OUT + d]);
    for (int k = 0; k < cntv; k++)
        acc += cvalp[base + k] * __half2float(Xwh[(long long)csrc[base + k] * W_OUT + d]);
    float dv = 1.f / (1.f + degsum[e * N_NODES + n]);
    lgcn[((long long)e * N_NODES + n) * W_OUT + d] = fmaxf(acc * dv, 0.f);
}

__global__ void att1(const float* __restrict__ lgcn, const float* __restrict__ attw,
                     float* __restrict__ attpart) {
    int g = blockIdx.x, e = blockIdx.y, d = threadIdx.x;
    float s = 0.f;
    int n0 = g * (N_NODES / ATT_G);
    for (int n = n0; n < n0 + N_NODES / ATT_G; n++)
        s += attw[n] * lgcn[((long long)e * N_NODES + n) * W_OUT + d];
    attpart[(e * ATT_G + g) * W_OUT + d] = s;
}

__global__ void att2(const float* __restrict__ attpart, const float* __restrict__ attb,
                     const float* __restrict__ attq, float* __restrict__ beta) {
    __shared__ float red[128];
    __shared__ float w[E_TYPES];
    int d = threadIdx.x;
    for (int e = 0; e < E_TYPES; e++) {
        float tot = 0.f;
#pragma unroll 8
        for (int g = 0; g < ATT_G; g++) tot += attpart[(e * ATT_G + g) * W_OUT + d];
        red[d] = tanhf(tot + attb[d]) * attq[d];
        __syncthreads();
        for (int o = 64; o; o >>= 1) {
            if (d < o) red[d] += red[d + o];
            __syncthreads();
        }
        if (d == 0) w[e] = red[0];
        __syncthreads();
    }
    if (d == 0) {
        float mx = w[0];
        for (int e = 1; e < E_TYPES; e++) mx = fmaxf(mx, w[e]);
        float ex[E_TYPES], s = 0.f;
        for (int e = 0; e < E_TYPES; e++) { ex[e] = expf(w[e] - mx); s += ex[e]; }
        for (int e = 0; e < E_TYPES; e++) beta[e] = (float)E_TYPES * ex[e] / s;
    }
}

__global__ void xcat_kernel(const float* __restrict__ lgcn, const float* __restrict__ X,
                            const float* __restrict__ beta, __half* __restrict__ Xcat) {
    long long idx = (long long)blockIdx.x * 256 + threadIdx.x;
    long long total = (long long)N_NODES * H0;
    if (idx >= total) return;
    int n = (int)(idx / H0), c = (int)(idx % H0);
    float v;
    if (c < E_TYPES * W_OUT) {
        int e = c >> 7, d = c & 127;
        v = beta[e] * lgcn[((long long)e * N_NODES + n) * W_OUT + d];
    } else {
        v = X[(long long)n * W_IN + (c - E_TYPES * W_OUT)];
    }
    Xcat[idx] = __float2half(v);
}

// ---------------- fp32 -> fp16 convert ----------------
__global__ void f2h_kernel(const float* __restrict__ src, __half* __restrict__ dst, int n4) {
    int i = blockIdx.x * 256 + threadIdx.x;
    if (i >= n4) return;
    float4 v = ((const float4*)src)[i];
    __half2 h0 = __floats2half2_rn(v.x, v.y);
    __half2 h1 = __floats2half2_rn(v.z, v.w);
    ((float2*)dst)[i] = make_float2(h2_as_f(h0), h2_as_f(h1));
}

// ---------------- W' prep (fp32): (1-bl)I + bl*Wl ----------------
__global__ void wprime_prep(const float* __restrict__ W, float* __restrict__ wp) {
    int l = blockIdx.x;
    float bl = logf(0.5f / (float)(l + 1) + 1.f);
    float omb = 1.f - bl;
    const float* Wl = W + (size_t)l * W_OUT * W_OUT;
    float* o = wp + (size_t)l * W_OUT * W_OUT;
    for (int i = threadIdx.x; i < W_OUT * W_OUT; i += 256) {
        int k = i >> 7, n = i & 127;
        o[i] = bl * Wl[i] + (k == n ? omb : 0.f);
    }
}

// ---------------- gather: h = 0.9*A_hat@x + 0.1*x0 (fp32 out) ----------------
__global__ __launch_bounds__(256) void gather4(
    const int* __restrict__ rowptr, const float2* __restrict__ cvp,
    const __half* __restrict__ xh, const float* __restrict__ x0,
    float* __restrict__ h_out) {
    __shared__ float ps[4][128];
    int t = threadIdx.x;
    int warp = t >> 5, lane = t & 31;
    int rloc = warp >> 1, half = warp & 1;
    int row = blockIdx.x * 4 + rloc;
    int ks = rowptr[row], ke = rowptr[row + 1];
    float a0 = 0.f, a1 = 0.f, a2 = 0.f, a3 = 0.f;
    for (int k0 = ks + half * 32; k0 < ke; k0 += 64) {
        int cnt = min(32, ke - k0);
        int cR = 0; float vR = 0.f;
        if (lane < cnt) {
            float2 cv = cvp[k0 + lane];
            cR = __float_as_int(cv.x);
            vR = cv.y;
        }
#pragma unroll 4
        for (int kk = 0; kk < cnt; kk++) {
            int c = __shfl_sync(0xffffffffu, cR, kk);
            float v = __shfl_sync(0xffffffffu, vR, kk);
            float2 raw = ((const float2*)(xh + (long long)c * W_OUT))[lane];
            __half2 p0 = *(__half2*)&raw.x;
            __half2 p1 = *(__half2*)&raw.y;
            float2 f0 = __half22float2(p0);
            float2 f1 = __half22float2(p1);
            a0 += v * f0.x; a1 += v * f0.y; a2 += v * f1.x; a3 += v * f1.y;
        }
    }
    if (half) {
        ps[rloc][lane * 4 + 0] = a0;
        ps[rloc][lane * 4 + 1] = a1;
        ps[rloc][lane * 4 + 2] = a2;
        ps[rloc][lane * 4 + 3] = a3;
    }
    __syncthreads();
    if (!half) {
        const float4 xv = ((const float4*)(x0 + (long long)row * W_OUT))[lane];
        float4 o;
        o.x = 0.9f * (a0 + ps[rloc][lane * 4 + 0]) + 0.1f * xv.x;
        o.y = 0.9f * (a1 + ps[rloc][lane * 4 + 1]) + 0.1f * xv.y;
        o.z = 0.9f * (a2 + ps[rloc][lane * 4 + 2]) + 0.1f * xv.z;
        o.w = 0.9f * (a3 + ps[rloc][lane * 4 + 3]) + 0.1f * xv.w;
        *(float4*)(h_out + (long long)row * W_OUT + lane * 4) = o;
    }
}

// ---------------- combine: out_fp16 = relu(h @ W') ----------------
__global__ __launch_bounds__(256) void combine32(
    const float* __restrict__ h, const float* __restrict__ wp,
    __half* __restrict__ xh_out) {
    __shared__ float hs[32 * 132];
    __shared__ float Ws[32 * 128];
    int t = threadIdx.x;
    int tx = t & 31, ty = t >> 5;
    int m0 = blockIdx.x * 32;
#pragma unroll
    for (int j = 0; j < 4; j++) {
        int e4 = t + 256 * j;
        int r = e4 >> 5, c4 = (e4 & 31) * 4;
        *(float4*)(hs + r * 132 + c4) =
            *(const float4*)(h + (size_t)(m0 + r) * W_OUT + c4);
    }
    float acc[4][4];
#pragma unroll
    for (int i = 0; i < 4; i++)
#pragma unroll
        for (int q = 0; q < 4; q++) acc[i][q] = 0.f;
    for (int k0 = 0; k0 < 128; k0 += 32) {
        __syncthreads();
#pragma unroll
        for (int j = 0; j < 4; j++) {
            int idx = t + 256 * j;
            int r = idx >> 5, c4 = (idx & 31) * 4;
            *(float4*)(Ws + r * 128 + c4) = *(const float4*)(wp + (k0 + r) * W_OUT + c4);
        }
        __syncthreads();
#pragma unroll
        for (int kk = 0; kk < 32; kk++) {
            float4 b = *(const float4*)(Ws + kk * 128 + tx * 4);
#pragma unroll
            for (int i = 0; i < 4; i++) {
                float a = hs[(ty * 4 + i) * 132 + k0 + kk];
                acc[i][0] += a * b.x; acc[i][1] += a * b.y;
                acc[i][2] += a * b.z; acc[i][3] += a * b.w;
            }
        }
    }
#pragma unroll
    for (int i = 0; i < 4; i++) {
        int row = m0 + ty * 4 + i;
        float v0 = fmaxf(acc[i][0], 0.f), v1 = fmaxf(acc[i][1], 0.f);
        float v2 = fmaxf(acc[i][2], 0.f), v3 = fmaxf(acc[i][3], 0.f);
        __half2 q0 = __floats2half2_rn(v0, v1);
        __half2 q1 = __floats2half2_rn(v2, v3);
        *(float2*)(xh_out + (size_t)row * W_OUT + tx * 4) =
            make_float2(h2_as_f(q0), h2_as_f(q1));
    }
}

// ---------------- head ----------------
__global__ void out_kernel(const float* __restrict__ Z, const int* __restrict__ tx,
                           const float* __restrict__ W2, const float* __restrict__ b2,
                           float* __restrict__ y) {
    int r = blockIdx.x;
    int t = threadIdx.x;
    __shared__ float z[W_OUT];
    z[t] = Z[(long long)tx[r] * W_OUT + t];
    __syncthreads();
    if (t < NUM_CLASS) {
        float s = b2[t];
        for (int k = 0; k < W_OUT; k++) s += z[k] * W2[k * NUM_CLASS + t];
        y[r * NUM_CLASS + t] = s;
    }
}

__global__ void loss_kernel(const float* __restrict__ y, const int* __restrict__ target,
                            float* __restrict__ out) {
    __shared__ float red[256];
    int tid = threadIdx.x;
    float part = 0.f;
    for (int r = tid; r < M_TGT; r += 256) {
        const float* yr = y + r * NUM_CLASS;
        float mx = yr[0];
#pragma unroll
        for (int c = 1; c < NUM_CLASS; c++) mx = fmaxf(mx, yr[c]);
        float se = 0.f;
#pragma unroll
        for (int c = 0; c < NUM_CLASS; c++) se += expf(yr[c] - mx);
        float lse = mx + logf(se);
        part += lse - yr[target[r]];
    }
    red[tid] = part;
    __syncthreads();
    for (int o = 128; o; o >>= 1) {
        if (tid < o) red[tid] += red[tid + o];
        __syncthreads();
    }
    if (tid == 0) out[0] = red[0] / (float)M_TGT;
}

// ---------------- launch ----------------
extern "C" void kernel_launch(void* const* d_in, const int* in_sizes, int n_in,
                              void* d_out, int out_size) {
    const float* A        = (const float*)d_in[0];
    const float* X        = (const float*)d_in[1];
    const int*   target_x = (const int*)d_in[2];
    const int*   target   = (const int*)d_in[3];
    const float* weight   = (const float*)d_in[4];
    const float* attw     = (const float*)d_in[5];
    const float* attb     = (const float*)d_in[6];
    const float* attq     = (const float*)d_in[7];
    const float* Wg       = (const float*)d_in[8];
    const float* bg       = (const float*)d_in[9];
    const float* W0       = (const float*)d_in[10];
    const float* b0       = (const float*)d_in[11];
    const float* Wconvs   = (const float*)d_in[12];
    const float* Wd1      = (const float*)d_in[13];
    const float* bd1      = (const float*)d_in[14];
    const float* W1       = (const float*)d_in[15];
    const float* b1       = (const float*)d_in[16];
    const float* W2       = (const float*)d_in[17];
    const float* b2       = (const float*)d_in[18];

    float *lgcn, *attpart, *beta, *x0, *Z2, *ybuf, *hbuf, *wp;
    float *dis, *cvalp;
    float2* cvp;
    __half *Xh, *Wgh, *weighth, *W0h, *Wd1h, *W1h, *Xgh, *Xwh, *Xcath;
    __half *xh0, *xhA, *xhB, *xlasth, *Z1h;
    int *cnt, *rowptr, *zinit, *csrcp, *rcolp;
    cudaGetSymbolAddress((void**)&Xh, g_Xh);
    cudaGetSymbolAddress((void**)&Wgh, g_Wgh);
    cudaGetSymbolAddress((void**)&weighth, g_weighth);
    cudaGetSymbolAddress((void**)&W0h, g_W0h);
    cudaGetSymbolAddress((void**)&Wd1h, g_Wd1h);
    cudaGetSymbolAddress((void**)&W1h, g_W1h);
    cudaGetSymbolAddress((void**)&Xgh, g_Xgh);
    cudaGetSymbolAddress((void**)&Xwh, g_Xwh);
    cudaGetSymbolAddress((void**)&lgcn, g_lgcn);
    cudaGetSymbolAddress((void**)&attpart, g_attpart);
    cudaGetSymbolAddress((void**)&beta, g_beta);
    cudaGetSymbolAddress((void**)&Xcath, g_Xcath);
    cudaGetSymbolAddress((void**)&x0, g_x0);
    cudaGetSymbolAddress((void**)&hbuf, g_hbuf);
    cudaGetSymbolAddress((void**)&wp, g_wprime);
    cudaGetSymbolAddress((void**)&xlasth, g_xlasth);
    cudaGetSymbolAddress((void**)&xh0, g_xh0);
    cudaGetSymbolAddress((void**)&xhA, g_xhA);
    cudaGetSymbolAddress((void**)&xhB, g_xhB);
    cudaGetSymbolAddress((void**)&Z1h, g_Z1h);
    cudaGetSymbolAddress((void**)&Z2, g_Z2);
    cudaGetSymbolAddress((void**)&ybuf, g_y);
    cudaGetSymbolAddress((void**)&cnt, g_cnt);
    cudaGetSymbolAddress((void**)&rowptr, g_rowptr);
    cudaGetSymbolAddress((void**)&dis, g_dis);
    cudaGetSymbolAddress((void**)&cvp, g_cv);
    cudaGetSymbolAddress((void**)&rcolp, g_rcol);
    cudaGetSymbolAddress((void**)&csrcp, g_csrc);
    cudaGetSymbolAddress((void**)&cvalp, g_cvalp);
    cudaGetSymbolAddress((void**)&zinit, g_zinit);

    int* ccnt = zinit;
    float* degsum = (float*)(zinit + E_TYPES * N_NODES);

    cudaMemsetAsync(zinit, 0, 2 * E_TYPES * N_NODES * sizeof(int));

    // 0) fp16 conversions of GEMM operands
    f2h_kernel<<<(N_NODES * W_IN / 4 + 255) / 256, 256>>>(X, Xh, N_NODES * W_IN / 4);
    f2h_kernel<<<(W_IN * W_IN / 4 + 255) / 256, 256>>>(Wg, Wgh, W_IN * W_IN / 4);
    f2h_kernel<<<(W_IN * W_OUT / 4 + 255) / 256, 256>>>(weight, weighth, W_IN * W_OUT / 4);
    f2h_kernel<<<(H0 * W_OUT / 4 + 255) / 256, 256>>>(W0, W0h, H0 * W_OUT / 4);
    f2h_kernel<<<(W_OUT * W_OUT / 4 + 255) / 256, 256>>>(Wd1, Wd1h, W_OUT * W_OUT / 4);
    f2h_kernel<<<(W_OUT * W_OUT / 4 + 255) / 256, 256>>>(W1, W1h, W_OUT * W_OUT / 4);

    // 1) Xg = leaky(X@Wg+bg) [fp16], Xw = leaky(Xg@weight) [fp16]  — HMMA
    hgemm<<<dim3(N_NODES / 128, W_IN / 128), 256>>>(Xh, Wgh, N_NODES, W_IN, W_IN,
                                                    bg, 2, nullptr, Xgh);
    hgemm<<<dim3(N_NODES / 128, 1), 256>>>(Xgh, weighth, N_NODES, W_OUT, W_IN,
                                           nullptr, 2, nullptr, Xwh);
    // 2) single-pass sparse structure + scan + compact + W' prep
    build_all<<<N_NODES, 256>>>(A, cnt, dis, ccnt, degsum, rcolp, csrcp, cvalp);
    scan_kernel<<<1, 1024>>>(cnt, rowptr);
    compact_csr<<<N_NODES, 256>>>(cnt, rowptr, rcolp, dis, cvp);
    wprime_prep<<<NUM_LAYERS, 256>>>(Wconvs, wp);
    // 3) lgcn (padded CSC, fp16 gather) + attention + concat + x0 (HMMA W0 GEMM)
    lgcn_pad<<<dim3(N_NODES, E_TYPES), 128>>>(Xwh, csrcp, cvalp, ccnt, degsum, lgcn);
    att1<<<dim3(ATT_G, E_TYPES), 128>>>(lgcn, attw, attpart);
    att2<<<1, 128>>>(attpart, attb, attq, beta);
    {
        long long total = (long long)N_NODES * H0;
        xcat_kernel<<<(unsigned)((total + 255) / 256), 256>>>(lgcn, X, beta, Xcath);
    }
    hgemm<<<dim3(N_NODES / 128, 1), 256>>>(Xcath, W0h, N_NODES, W_OUT, H0,
                                           b0, 1, x0, xh0);
    // 4) 64 GCNII layers: gather (BW-bound) + combine (fp32 W' GEMM)
    const __half* xin = xh0;
    __half* bufs[2] = {xhA, xhB};
    for (int l = 0; l < NUM_LAYERS; l++) {
        bool last = (l == NUM_LAYERS - 1);
        __half* xhout = last ? xlasth : bufs[l & 1];
        gather4<<<N_NODES / 4, 256>>>(rowptr, cvp, xin, x0, hbuf);
        combine32<<<N_NODES / 32, 256>>>(hbuf, wp + (size_t)l * W_OUT * W_OUT, xhout);
        xin = xhout;
    }
    // 5) head — HMMA
    hgemm<<<dim3(N_NODES / 128, 1), 256>>>(xlasth, Wd1h, N_NODES, W_OUT, W_OUT,
                                           bd1, 2, nullptr, Z1h);
    hgemm<<<dim3(N_NODES / 128, 1), 256>>>(Z1h, W1h, N_NODES, W_OUT, W_OUT,
                                           b1, 2, Z2, nullptr);
    float* yout;
    bool with_loss;
    if (out_size >= M_TGT * NUM_CLASS + 1) { yout = (float*)d_out + 1; with_loss = true; }
    else if (out_size == M_TGT * NUM_CLASS) { yout = (float*)d_out; with_loss = false; }
    else { yout = ybuf; with_loss = true; }
    out_kernel<<<M_TGT, 128>>>(Z2, target_x, W2, b2, yout);
    if (with_loss) loss_kernel<<<1, 256>>>(yout, target, (float*)d_out);
}

// round 17
// speedup vs baseline: 1.9529x; 1.0612x over previous
#include <cuda_runtime.h>
#include <cuda_fp16.h>
#include <math.h>
#include <stdint.h>

#define N_NODES 4096
#define E_TYPES 5
#define W_IN 512
#define W_OUT 128
#define NUM_CLASS 16
#define M_TGT 1024
#define NUM_LAYERS 64
#define H0 (W_IN + E_TYPES * W_OUT)   // 1152
#define NNZ_CAP 2097152
#define ATT_G 128
#define CAP_R 384
#define CAP_C 128

// ---------------- static scratch ----------------
__device__ __half g_Xh[N_NODES * W_IN];
__device__ __half g_Wgh[W_IN * W_IN];
__device__ __half g_weighth[W_IN * W_OUT];
__device__ __half g_W0h[H0 * W_OUT];
__device__ __half g_Wd1h[W_OUT * W_OUT];
__device__ __half g_W1h[W_OUT * W_OUT];
__device__ __half g_Wch[(size_t)NUM_LAYERS * W_OUT * W_OUT];  // Wconvs fp16
__device__ __half g_Xgh[N_NODES * W_IN];
__device__ __half g_Xwh[N_NODES * W_OUT];
__device__ float g_lgcn[E_TYPES * N_NODES * W_OUT];
__device__ float g_attpart[E_TYPES * ATT_G * W_OUT];
__device__ float g_beta[E_TYPES];
__device__ __half g_Xcath[N_NODES * H0];
__device__ float g_x0[N_NODES * W_OUT];
__device__ float g_hbuf[N_NODES * W_OUT];        // h fp32 (residual path)
__device__ __half g_hh[N_NODES * W_OUT];         // h fp16 (HMMA A operand)
__device__ __half g_xlasth[N_NODES * W_OUT];
__device__ __half g_xh0[N_NODES * W_OUT];
__device__ __half g_xhA[N_NODES * W_OUT];
__device__ __half g_xhB[N_NODES * W_OUT];
__device__ __half g_Z1h[N_NODES * W_OUT];
__device__ float g_Z2[N_NODES * W_OUT];
__device__ float g_y[M_TGT * NUM_CLASS];
__device__ int   g_cnt[N_NODES];
__device__ int   g_rowptr[N_NODES + 1];
__device__ float g_dis[N_NODES];
__device__ float2 g_cv[NNZ_CAP];                 // interleaved (col_bits, val)
__device__ int   g_rcol[(size_t)N_NODES * CAP_R];
__device__ int   g_csrc[(size_t)E_TYPES * N_NODES * CAP_C];
__device__ float g_cvalp[(size_t)E_TYPES * N_NODES * CAP_C];
__device__ int   g_zinit[2 * E_TYPES * N_NODES]; // ccnt | degsum(float)

// ---------------- helpers ----------------
__device__ __forceinline__ float h2_as_f(__half2 h) {
    return __uint_as_float(*(unsigned*)&h);
}
__device__ __forceinline__ uint32_t smem_u32(const void* p) {
    uint32_t a;
    asm("{ .reg .u64 t; cvta.to.shared.u64 t, %1; cvt.u32.u64 %0, t; }" : "=r"(a) : "l"(p));
    return a;
}
__device__ __forceinline__ void cpa16(uint32_t dst, const void* src) {
    asm volatile("cp.async.cg.shared.global [%0], [%1], 16;" :: "r"(dst), "l"(src));
}
__device__ __forceinline__ void ldmx4(uint32_t& r0, uint32_t& r1, uint32_t& r2,
                                      uint32_t& r3, uint32_t addr) {
    asm volatile("ldmatrix.sync.aligned.m8n8.x4.shared.b16 {%0,%1,%2,%3}, [%4];"
                 : "=r"(r0), "=r"(r1), "=r"(r2), "=r"(r3) : "r"(addr));
}
__device__ __forceinline__ void ldmx4t(uint32_t& r0, uint32_t& r1, uint32_t& r2,
                                       uint32_t& r3, uint32_t addr) {
    asm volatile("ldmatrix.sync.aligned.m8n8.x4.trans.shared.b16 {%0,%1,%2,%3}, [%4];"
                 : "=r"(r0), "=r"(r1), "=r"(r2), "=r"(r3) : "r"(addr));
}
__device__ __forceinline__ void mma16816(float* c, uint32_t a0, uint32_t a1, uint32_t a2,
                                         uint32_t a3, uint32_t b0, uint32_t b1) {
    asm volatile(
        "mma.sync.aligned.m16n8k16.row.col.f32.f16.f16.f32 "
        "{%0,%1,%2,%3}, {%4,%5,%6,%7}, {%8,%9}, {%0,%1,%2,%3};"
        : "+f"(c[0]), "+f"(c[1]), "+f"(c[2]), "+f"(c[3])
        : "r"(a0), "r"(a1), "r"(a2), "r"(a3), "r"(b0), "r"(b1));
}

// ---------------- generic fp16 HMMA GEMM with epilogue ----------------
__global__ __launch_bounds__(256, 1) void hgemm(
    const __half* __restrict__ A, const __half* __restrict__ B,
    int M, int N, int K, const float* __restrict__ bias, int act,
    float* __restrict__ Cf, __half* __restrict__ Ch) {
    __shared__ __half As[2][128 * 40];
    __shared__ __half Bs[2][32 * 136];
    int t = threadIdx.x, w = t >> 5, lane = t & 31;
    int m0 = blockIdx.x * 128, n0 = blockIdx.y * 128;
    const __half* Ag = A + (size_t)m0 * K;
    const __half* Bg = B + n0;
    uint32_t asb[2] = {smem_u32(As[0]), smem_u32(As[1])};
    uint32_t bsb[2] = {smem_u32(Bs[0]), smem_u32(Bs[1])};

    auto prefetch = [&](int i, int buf) {
#pragma unroll
        for (int j = 0; j < 2; j++) {
            int cid = t + 256 * j;
            int r = cid >> 2, co = (cid & 3) * 8;
            cpa16(asb[buf] + (r * 40 + co) * 2, Ag + (size_t)r * K + i * 32 + co);
            int rb = cid >> 4, cb = (cid & 15) * 8;
            cpa16(bsb[buf] + (rb * 136 + cb) * 2, Bg + (size_t)(i * 32 + rb) * N + cb);
        }
        asm volatile("cp.async.commit_group;" ::: "memory");
    };
    prefetch(0, 0);
    prefetch(1, 1);

    int wm = w >> 2, wn = w & 3;
    float c[4][4][4];
#pragma unroll
    for (int mi = 0; mi < 4; mi++)
#pragma unroll
        for (int nj = 0; nj < 4; nj++)
#pragma unroll
            for (int q = 0; q < 4; q++) c[mi][nj][q] = 0.f;

    int niter = K / 32;
    for (int i = 0; i < niter; i++) {
        asm volatile("cp.async.wait_group 1;" ::: "memory");
        __syncthreads();
        int buf = i & 1;
        uint32_t ab = asb[buf], bb = bsb[buf];
#pragma unroll
        for (int kk = 0; kk < 2; kk++) {
            uint32_t a[4][4];
#pragma unroll
            for (int mi = 0; mi < 4; mi++) {
                int row = wm * 64 + mi * 16 + (lane & 15);
                int col = kk * 16 + (lane >> 4) * 8;
                ldmx4(a[mi][0], a[mi][1], a[mi][2], a[mi][3], ab + (row * 40 + col) * 2);
            }
            uint32_t b[2][4];
#pragma unroll
            for (int ng = 0; ng < 2; ng++) {
                int row = kk * 16 + (lane & 15);
                int col = wn * 32 + ng * 16 + (lane >> 4) * 8;
                ldmx4t(b[ng][0], b[ng][1], b[ng][2], b[ng][3], bb + (row * 136 + col) * 2);
            }
#pragma unroll
            for (int mi = 0; mi < 4; mi++)
#pragma unroll
                for (int nj = 0; nj < 4; nj++)
                    mma16816(c[mi][nj], a[mi][0], a[mi][1], a[mi][2], a[mi][3],
                             b[nj >> 1][(nj & 1) * 2], b[nj >> 1][(nj & 1) * 2 + 1]);
        }
        __syncthreads();
        if (i + 2 < niter) prefetch(i + 2, buf);
        else asm volatile("cp.async.commit_group;" ::: "memory");
    }

#pragma unroll
    for (int mi = 0; mi < 4; mi++)
#pragma unroll
        for (int nj = 0; nj < 4; nj++) {
            int rl = wm * 64 + mi * 16 + (lane >> 2);
            int cl = wn * 32 + nj * 8 + (lane & 3) * 2;
            float bz0 = bias ? bias[n0 + cl] : 0.f;
            float bz1 = bias ? bias[n0 + cl + 1] : 0.f;
#pragma unroll
            for (int half2i = 0; half2i < 2; half2i++) {
                int row = m0 + rl + half2i * 8;
                float v0 = c[mi][nj][half2i * 2 + 0] + bz0;
                float v1 = c[mi][nj][half2i * 2 + 1] + bz1;
                if (act == 1) { v0 = fmaxf(v0, 0.f); v1 = fmaxf(v1, 0.f); }
                else if (act == 2) {
                    v0 = (v0 >= 0.f) ? v0 : 0.01f * v0;
                    v1 = (v1 >= 0.f) ? v1 : 0.01f * v1;
                }
                if (Cf) *(float2*)(Cf + (size_t)row * N + n0 + cl) = make_float2(v0, v1);
                if (Ch) {
                    __half2 q = __floats2half2_rn(v0, v1);
                    *(unsigned*)(Ch + (size_t)row * N + n0 + cl) = *(unsigned*)&q;
                }
            }
        }
}

// ---------------- single-pass A scan ----------------
__global__ void build_all(const float* __restrict__ A, int* __restrict__ cnt,
                          float* __restrict__ dis, int* __restrict__ ccnt,
                          float* __restrict__ degsum, int* __restrict__ rcol,
                          int* __restrict__ csrc, float* __restrict__ cvalp) {
    int i = blockIdx.x;
    int tid = threadIdx.x;
    __shared__ int rcount;
    if (tid == 0) rcount = 0;
    __syncthreads();
    int* rc = rcol + (size_t)i * CAP_R;
    for (int j = tid; j < N_NODES; j += 256) {
        const float* ap = A + ((long long)i * N_NODES + j) * E_TYPES;
        float a[E_TYPES];
#pragma unroll
        for (int e = 0; e < E_TYPES; e++) a[e] = ap[e];
        bool nz = (j == i);
#pragma unroll
        for (int e = 0; e < E_TYPES; e++) nz |= (a[e] != 0.f);
        if (nz) {
            int slot = atomicAdd(&rcount, 1);
            if (slot < CAP_R) rc[slot] = j;
        }
        if (j != i) {
#pragma unroll
            for (int e = 0; e < E_TYPES; e++) {
                if (a[e] != 0.f) {
                    int cs = atomicAdd(&ccnt[e * N_NODES + j], 1);
                    if (cs < CAP_C) {
                        size_t p = (size_t)(e * N_NODES + j) * CAP_C + cs;
                        csrc[p] = i;
                        cvalp[p] = a[e];
                    }
                    atomicAdd(&degsum[e * N_NODES + j], a[e]);
                }
            }
        }
    }
    __syncthreads();
    if (tid == 0) {
        int c = min(rcount, CAP_R);
        cnt[i] = c;
        dis[i] = rsqrtf((float)rcount);
    }
}

__global__ void scan_kernel(const int* __restrict__ cnt, int* __restrict__ rowptr) {
    __shared__ int warpsum[32];
    int t = threadIdx.x;
    int v[4], s = 0;
#pragma unroll
    for (int j = 0; j < 4; j++) { v[j] = cnt[t * 4 + j]; s += v[j]; }
    int lane = t & 31, warp = t >> 5;
    int x = s;
#pragma unroll
    for (int o = 1; o < 32; o <<= 1) {
        int y = __shfl_up_sync(0xffffffffu, x, o);
        if (lane >= o) x += y;
    }
    if (lane == 31) warpsum[warp] = x;
    __syncthreads();
    if (warp == 0) {
        int w = warpsum[lane];
#pragma unroll
        for (int o = 1; o < 32; o <<= 1) {
            int y = __shfl_up_sync(0xffffffffu, w, o);
            if (lane >= o) w += y;
        }
        warpsum[lane] = w;
    }
    __syncthreads();
    int excl = x - s + (warp ? warpsum[warp - 1] : 0);
    int run = excl;
    if (t == 0) rowptr[0] = 0;
#pragma unroll
    for (int j = 0; j < 4; j++) { run += v[j]; rowptr[t * 4 + j + 1] = run; }
}

__global__ void compact_csr(const int* __restrict__ cnt, const int* __restrict__ rowptr,
                            const int* __restrict__ rcol, const float* __restrict__ dis,
                            float2* __restrict__ cv) {
    int i = blockIdx.x;
    int n = cnt[i];
    int base = rowptr[i];
    float di = dis[i];
    const int* rc = rcol + (size_t)i * CAP_R;
    for (int s = threadIdx.x; s < n; s += 256) {
        int j = rc[s];
        cv[base + s] = make_float2(__int_as_float(j), di * dis[j]);
    }
}

// ---------------- lgcn from padded CSC ----------------
__global__ void lgcn_pad(const __half* __restrict__ Xwh, const int* __restrict__ csrc,
                         const float* __restrict__ cvalp, const int* __restrict__ ccnt,
                         const float* __restrict__ degsum, float* __restrict__ lgcn) {
    int n = blockIdx.x, e = blockIdx.y, d = threadIdx.x;
    int cntv = min(ccnt[e * N_NODES + n], CAP_C);
    size_t base = (size_t)(e * N_NODES + n) * CAP_C;
    float acc = __half2float(Xwh[(long long)n * W_OUT + d]);
    for (int k = 0; k < cntv; k++)
        acc += cvalp[base + k] * __half2float(Xwh[(long long)csrc[base + k] * W_OUT + d]);
    float dv = 1.f / (1.f + degsum[e * N_NODES + n]);
    lgcn[((long long)e * N_NODES + n) * W_OUT + d] = fmaxf(acc * dv, 0.f);
}

__global__ void att1(const float* __restrict__ lgcn, const float* __restrict__ attw,
                     float* __restrict__ attpart) {
    int g = blockIdx.x, e = blockIdx.y, d = threadIdx.x;
    float s = 0.f;
    int n0 = g * (N_NODES / ATT_G);
    for (int n = n0; n < n0 + N_NODES / ATT_G; n++)
        s += attw[n] * lgcn[((long long)e * N_NODES + n) * W_OUT + d];
    attpart[(e * ATT_G + g) * W_OUT + d] = s;
}

__global__ void att2(const float* __restrict__ attpart, const float* __restrict__ attb,
                     const float* __restrict__ attq, float* __restrict__ beta) {
    __shared__ float red[128];
    __shared__ float w[E_TYPES];
    int d = threadIdx.x;
    for (int e = 0; e < E_TYPES; e++) {
        float tot = 0.f;
#pragma unroll 8
        for (int g = 0; g < ATT_G; g++) tot += attpart[(e * ATT_G + g) * W_OUT + d];
        red[d] = tanhf(tot + attb[d]) * attq[d];
        __syncthreads();
        for (int o = 64; o; o >>= 1) {
            if (d < o) red[d] += red[d + o];
            __syncthreads();
        }
        if (d == 0) w[e] = red[0];
        __syncthreads();
    }
    if (d == 0) {
        float mx = w[0];
        for (int e = 1; e < E_TYPES; e++) mx = fmaxf(mx, w[e]);
        float ex[E_TYPES], s = 0.f;
        for (int e = 0; e < E_TYPES; e++) { ex[e] = expf(w[e] - mx); s += ex[e]; }
        for (int e = 0; e < E_TYPES; e++) beta[e] = (float)E_TYPES * ex[e] / s;
    }
}

__global__ void xcat_kernel(const float* __restrict__ lgcn, const float* __restrict__ X,
                            const float* __restrict__ beta, __half* __restrict__ Xcat) {
    long long idx = (long long)blockIdx.x * 256 + threadIdx.x;
    long long total = (long long)N_NODES * H0;
    if (idx >= total) return;
    int n = (int)(idx / H0), c = (int)(idx % H0);
    float v;
    if (c < E_TYPES * W_OUT) {
        int e = c >> 7, d = c & 127;
        v = beta[e] * lgcn[((long long)e * N_NODES + n) * W_OUT + d];
    } else {
        v = X[(long long)n * W_IN + (c - E_TYPES * W_OUT)];
    }
    Xcat[idx] = __float2half(v);
}

// ---------------- fp32 -> fp16 convert ----------------
__global__ void f2h_kernel(const float* __restrict__ src, __half* __restrict__ dst, int n4) {
    int i = blockIdx.x * 256 + threadIdx.x;
    if (i >= n4) return;
    float4 v = ((const float4*)src)[i];
    __half2 h0 = __floats2half2_rn(v.x, v.y);
    __half2 h1 = __floats2half2_rn(v.z, v.w);
    ((float2*)dst)[i] = make_float2(h2_as_f(h0), h2_as_f(h1));
}

// ---------------- gather: h = 0.9*A_hat@x + 0.1*x0 (fp32 + fp16 out) ----------------
__global__ __launch_bounds__(256) void gather4(
    const int* __restrict__ rowptr, const float2* __restrict__ cvp,
    const __half* __restrict__ xh, const float* __restrict__ x0,
    float* __restrict__ h_out, __half* __restrict__ hh_out) {
    __shared__ float ps[4][128];
    int t = threadIdx.x;
    int warp = t >> 5, lane = t & 31;
    int rloc = warp >> 1, half = warp & 1;
    int row = blockIdx.x * 4 + rloc;
    int ks = rowptr[row], ke = rowptr[row + 1];
    float a0 = 0.f, a1 = 0.f, a2 = 0.f, a3 = 0.f;
    for (int k0 = ks + half * 32; k0 < ke; k0 += 64) {
        int cnt = min(32, ke - k0);
        int cR = 0; float vR = 0.f;
        if (lane < cnt) {
            float2 cv = cvp[k0 + lane];
            cR = __float_as_int(cv.x);
            vR = cv.y;
        }
#pragma unroll 4
        for (int kk = 0; kk < cnt; kk++) {
            int c = __shfl_sync(0xffffffffu, cR, kk);
            float v = __shfl_sync(0xffffffffu, vR, kk);
            float2 raw = ((const float2*)(xh + (long long)c * W_OUT))[lane];
            __half2 p0 = *(__half2*)&raw.x;
            __half2 p1 = *(__half2*)&raw.y;
            float2 f0 = __half22float2(p0);
            float2 f1 = __half22float2(p1);
            a0 += v * f0.x; a1 += v * f0.y; a2 += v * f1.x; a3 += v * f1.y;
        }
    }
    if (half) {
        ps[rloc][lane * 4 + 0] = a0;
        ps[rloc][lane * 4 + 1] = a1;
        ps[rloc][lane * 4 + 2] = a2;
        ps[rloc][lane * 4 + 3] = a3;
    }
    __syncthreads();
    if (!half) {
        const float4 xv = ((const float4*)(x0 + (long long)row * W_OUT))[lane];
        float4 o;
        o.x = 0.9f * (a0 + ps[rloc][lane * 4 + 0]) + 0.1f * xv.x;
        o.y = 0.9f * (a1 + ps[rloc][lane * 4 + 1]) + 0.1f * xv.y;
        o.z = 0.9f * (a2 + ps[rloc][lane * 4 + 2]) + 0.1f * xv.z;
        o.w = 0.9f * (a3 + ps[rloc][lane * 4 + 3]) + 0.1f * xv.w;
        *(float4*)(h_out + (long long)row * W_OUT + lane * 4) = o;
        __half2 q0 = __floats2half2_rn(o.x, o.y);
        __half2 q1 = __floats2half2_rn(o.z, o.w);
        *(float2*)(hh_out + (long long)row * W_OUT + lane * 4) =
            make_float2(h2_as_f(q0), h2_as_f(q1));
    }
}

// ---------------- combine (HMMA): out = relu((1-bl)*h_f32 + bl*(h_f16 @ Wl_f16)) ----------------
// grid 64 (64-row tiles), 256 thr = 8 warps (2x4), warp tile 32x32, K=128.
__global__ __launch_bounds__(256) void combine_hmma(
    const __half* __restrict__ hh, const __half* __restrict__ Wlh,
    const float* __restrict__ hres, float bl, __half* __restrict__ xh_out) {
    __shared__ __half As[2][64 * 40];
    __shared__ __half Bs[2][32 * 136];
    int t = threadIdx.x, w = t >> 5, lane = t & 31;
    int m0 = blockIdx.x * 64;
    const __half* Ag = hh + (size_t)m0 * W_OUT;
    const __half* Bg = Wlh;
    uint32_t asb[2] = {smem_u32(As[0]), smem_u32(As[1])};
    uint32_t bsb[2] = {smem_u32(Bs[0]), smem_u32(Bs[1])};

    auto prefetch = [&](int i, int buf) {
        {   // A: 64 rows x 32 cols = 2048 halfs = 256 thr x 8
            int r = t >> 2, co = (t & 3) * 8;
            cpa16(asb[buf] + (r * 40 + co) * 2, Ag + (size_t)r * W_OUT + i * 32 + co);
        }
#pragma unroll
        for (int j = 0; j < 2; j++) {   // B: 32 rows x 128 cols = 4096 halfs
            int cid = t + 256 * j;
            int rb = cid >> 4, cb = (cid & 15) * 8;
            cpa16(bsb[buf] + (rb * 136 + cb) * 2, Bg + (size_t)(i * 32 + rb) * W_OUT + cb);
        }
        asm volatile("cp.async.commit_group;" ::: "memory");
    };
    prefetch(0, 0);
    prefetch(1, 1);

    int wm = w >> 2, wn = w & 3;
    float c[2][4][4];
#pragma unroll
    for (int mi = 0; mi < 2; mi++)
#pragma unroll
        for (int nj = 0; nj < 4; nj++)
#pragma unroll
            for (int q = 0; q < 4; q++) c[mi][nj][q] = 0.f;

    for (int i = 0; i < 4; i++) {
        asm volatile("cp.async.wait_group 1;" ::: "memory");
        __syncthreads();
        int buf = i & 1;
        uint32_t ab = asb[buf], bb = bsb[buf];
#pragma unroll
        for (int kk = 0; kk < 2; kk++) {
            uint32_t a[2][4];
#pragma unroll
            for (int mi = 0; mi < 2; mi++) {
                int row = wm * 32 + mi * 16 + (lane & 15);
                int col = kk * 16 + (lane >> 4) * 8;
                ldmx4(a[mi][0], a[mi][1], a[mi][2], a[mi][3], ab + (row * 40 + col) * 2);
            }
            uint32_t b[2][4];
#pragma unroll
            for (int ng = 0; ng < 2; ng++) {
                int row = kk * 16 + (lane & 15);
                int col = wn * 32 + ng * 16 + (lane >> 4) * 8;
                ldmx4t(b[ng][0], b[ng][1], b[ng][2], b[ng][3], bb + (row * 136 + col) * 2);
            }
#pragma unroll
            for (int mi = 0; mi < 2; mi++)
#pragma unroll
                for (int nj = 0; nj < 4; nj++)
                    mma16816(c[mi][nj], a[mi][0], a[mi][1], a[mi][2], a[mi][3],
                             b[nj >> 1][(nj & 1) * 2], b[nj >> 1][(nj & 1) * 2 + 1]);
        }
        __syncthreads();
        if (i + 2 < 4) prefetch(i + 2, buf);
        else asm volatile("cp.async.commit_group;" ::: "memory");
    }

    float omb = 1.f - bl;
#pragma unroll
    for (int mi = 0; mi < 2; mi++)
#pragma unroll
        for (int nj = 0; nj < 4; nj++) {
            int rl = wm * 32 + mi * 16 + (lane >> 2);
            int cl = wn * 32 + nj * 8 + (lane & 3) * 2;
#pragma unroll
            for (int h2i = 0; h2i < 2; h2i++) {
                int row = m0 + rl + h2i * 8;
                float2 rv = *(const float2*)(hres + (size_t)row * W_OUT + cl);
                float v0 = fmaxf(bl * c[mi][nj][h2i * 2 + 0] + omb * rv.x, 0.f);
                float v1 = fmaxf(bl * c[mi][nj][h2i * 2 + 1] + omb * rv.y, 0.f);
                __half2 q = __floats2half2_rn(v0, v1);
                *(unsigned*)(xh_out + (size_t)row * W_OUT + cl) = *(unsigned*)&q;
            }
        }
}

// ---------------- head ----------------
__global__ void out_kernel(const float* __restrict__ Z, const int* __restrict__ tx,
                           const float* __restrict__ W2, const float* __restrict__ b2,
                           float* __restrict__ y) {
    int r = blockIdx.x;
    int t = threadIdx.x;
    __shared__ float z[W_OUT];
    z[t] = Z[(long long)tx[r] * W_OUT + t];
    __syncthreads();
    if (t < NUM_CLASS) {
        float s = b2[t];
        for (int k = 0; k < W_OUT; k++) s += z[k] * W2[k * NUM_CLASS + t];
        y[r * NUM_CLASS + t] = s;
    }
}

__global__ void loss_kernel(const float* __restrict__ y, const int* __restrict__ target,
                            float* __restrict__ out) {
    __shared__ float red[256];
    int tid = threadIdx.x;
    float part = 0.f;
    for (int r = tid; r < M_TGT; r += 256) {
        const float* yr = y + r * NUM_CLASS;
        float mx = yr[0];
#pragma unroll
        for (int c = 1; c < NUM_CLASS; c++) mx = fmaxf(mx, yr[c]);
        float se = 0.f;
#pragma unroll
        for (int c = 0; c < NUM_CLASS; c++) se += expf(yr[c] - mx);
        float lse = mx + logf(se);
        part += lse - yr[target[r]];
    }
    red[tid] = part;
    __syncthreads();
    for (int o = 128; o; o >>= 1) {
        if (tid < o) red[tid] += red[tid + o];
        __syncthreads();
    }
    if (tid == 0) out[0] = red[0] / (float)M_TGT;
}

// ---------------- launch ----------------
extern "C" void kernel_launch(void* const* d_in, const int* in_sizes, int n_in,
                              void* d_out, int out_size) {
    const float* A        = (const float*)d_in[0];
    const float* X        = (const float*)d_in[1];
    const int*   target_x = (const int*)d_in[2];
    const int*   target   = (const int*)d_in[3];
    const float* weight   = (const float*)d_in[4];
    const float* attw     = (const float*)d_in[5];
    const float* attb     = (const float*)d_in[6];
    const float* attq     = (const float*)d_in[7];
    const float* Wg       = (const float*)d_in[8];
    const float* bg       = (const float*)d_in[9];
    const float* W0       = (const float*)d_in[10];
    const float* b0       = (const float*)d_in[11];
    const float* Wconvs   = (const float*)d_in[12];
    const float* Wd1      = (const float*)d_in[13];
    const float* bd1      = (const float*)d_in[14];
    const float* W1       = (const float*)d_in[15];
    const float* b1       = (const float*)d_in[16];
    const float* W2       = (const float*)d_in[17];
    const float* b2       = (const float*)d_in[18];

    float *lgcn, *attpart, *beta, *x0, *Z2, *ybuf, *hbuf;
    float *dis, *cvalp;
    float2* cvp;
    __half *Xh, *Wgh, *weighth, *W0h, *Wd1h, *W1h, *Wch, *Xgh, *Xwh, *Xcath;
    __half *xh0, *xhA, *xhB, *xlasth, *Z1h, *hh;
    int *cnt, *rowptr, *zinit, *csrcp, *rcolp;
    cudaGetSymbolAddress((void**)&Xh, g_Xh);
    cudaGetSymbolAddress((void**)&Wgh, g_Wgh);
    cudaGetSymbolAddress((void**)&weighth, g_weighth);
    cudaGetSymbolAddress((void**)&W0h, g_W0h);
    cudaGetSymbolAddress((void**)&Wd1h, g_Wd1h);
    cudaGetSymbolAddress((void**)&W1h, g_W1h);
    cudaGetSymbolAddress((void**)&Wch, g_Wch);
    cudaGetSymbolAddress((void**)&Xgh, g_Xgh);
    cudaGetSymbolAddress((void**)&Xwh, g_Xwh);
    cudaGetSymbolAddress((void**)&lgcn, g_lgcn);
    cudaGetSymbolAddress((void**)&attpart, g_attpart);
    cudaGetSymbolAddress((void**)&beta, g_beta);
    cudaGetSymbolAddress((void**)&Xcath, g_Xcath);
    cudaGetSymbolAddress((void**)&x0, g_x0);
    cudaGetSymbolAddress((void**)&hbuf, g_hbuf);
    cudaGetSymbolAddress((void**)&hh, g_hh);
    cudaGetSymbolAddress((void**)&xlasth, g_xlasth);
    cudaGetSymbolAddress((void**)&xh0, g_xh0);
    cudaGetSymbolAddress((void**)&xhA, g_xhA);
    cudaGetSymbolAddress((void**)&xhB, g_xhB);
    cudaGetSymbolAddress((void**)&Z1h, g_Z1h);
    cudaGetSymbolAddress((void**)&Z2, g_Z2);
    cudaGetSymbolAddress((void**)&ybuf, g_y);
    cudaGetSymbolAddress((void**)&cnt, g_cnt);
    cudaGetSymbolAddress((void**)&rowptr, g_rowptr);
    cudaGetSymbolAddress((void**)&dis, g_dis);
    cudaGetSymbolAddress((void**)&cvp, g_cv);
    cudaGetSymbolAddress((void**)&rcolp, g_rcol);
    cudaGetSymbolAddress((void**)&csrcp, g_csrc);
    cudaGetSymbolAddress((void**)&cvalp, g_cvalp);
    cudaGetSymbolAddress((void**)&zinit, g_zinit);

    int* ccnt = zinit;
    float* degsum = (float*)(zinit + E_TYPES * N_NODES);

    cudaMemsetAsync(zinit, 0, 2 * E_TYPES * N_NODES * sizeof(int));

    // 0) fp16 conversions of GEMM operands (incl. all 64 conv weights)
    f2h_kernel<<<(N_NODES * W_IN / 4 + 255) / 256, 256>>>(X, Xh, N_NODES * W_IN / 4);
    f2h_kernel<<<(W_IN * W_IN / 4 + 255) / 256, 256>>>(Wg, Wgh, W_IN * W_IN / 4);
    f2h_kernel<<<(W_IN * W_OUT / 4 + 255) / 256, 256>>>(weight, weighth, W_IN * W_OUT / 4);
    f2h_kernel<<<(H0 * W_OUT / 4 + 255) / 256, 256>>>(W0, W0h, H0 * W_OUT / 4);
    f2h_kernel<<<(W_OUT * W_OUT / 4 + 255) / 256, 256>>>(Wd1, Wd1h, W_OUT * W_OUT / 4);
    f2h_kernel<<<(W_OUT * W_OUT / 4 + 255) / 256, 256>>>(W1, W1h, W_OUT * W_OUT / 4);
    f2h_kernel<<<(NUM_LAYERS * W_OUT * W_OUT / 4 + 255) / 256, 256>>>(
        Wconvs, Wch, NUM_LAYERS * W_OUT * W_OUT / 4);

    // 1) Xg = leaky(X@Wg+bg) [fp16], Xw = leaky(Xg@weight) [fp16]  — HMMA
    hgemm<<<dim3(N_NODES / 128, W_IN / 128), 256>>>(Xh, Wgh, N_NODES, W_IN, W_IN,
                                                    bg, 2, nullptr, Xgh);
    hgemm<<<dim3(N_NODES / 128, 1), 256>>>(Xgh, weighth, N_NODES, W_OUT, W_IN,
                                           nullptr, 2, nullptr, Xwh);
    // 2) single-pass sparse structure + scan + compact
    build_all<<<N_NODES, 256>>>(A, cnt, dis, ccnt, degsum, rcolp, csrcp, cvalp);
    scan_kernel<<<1, 1024>>>(cnt, rowptr);
    compact_csr<<<N_NODES, 256>>>(cnt, rowptr, rcolp, dis, cvp);
    // 3) lgcn + attention + concat + x0 (HMMA W0 GEMM)
    lgcn_pad<<<dim3(N_NODES, E_TYPES), 128>>>(Xwh, csrcp, cvalp, ccnt, degsum, lgcn);
    att1<<<dim3(ATT_G, E_TYPES), 128>>>(lgcn, attw, attpart);
    att2<<<1, 128>>>(attpart, attb, attq, beta);
    {
        long long total = (long long)N_NODES * H0;
        xcat_kernel<<<(unsigned)((total + 255) / 256), 256>>>(lgcn, X, beta, Xcath);
    }
    hgemm<<<dim3(N_NODES / 128, 1), 256>>>(Xcath, W0h, N_NODES, W_OUT, H0,
                                           b0, 1, x0, xh0);
    // 4) 64 GCNII layers: gather (BW-bound) + combine (HMMA, exact fp32 residual)
    const __half* xin = xh0;
    __half* bufs[2] = {xhA, xhB};
    for (int l = 0; l < NUM_LAYERS; l++) {
        bool last = (l == NUM_LAYERS - 1);
        float bl = logf(0.5f / (float)(l + 1) + 1.f);
        __half* xhout = last ? xlasth : bufs[l & 1];
        gather4<<<N_NODES / 4, 256>>>(rowptr, cvp, xin, x0, hbuf, hh);
        combine_hmma<<<N_NODES / 64, 256>>>(hh, Wch + (size_t)l * W_OUT * W_OUT,
                                            hbuf, bl, xhout);
        xin = xhout;
    }
    // 5) head — HMMA
    hgemm<<<dim3(N_NODES / 128, 1), 256>>>(xlasth, Wd1h, N_NODES, W_OUT, W_OUT,
                                           bd1, 2, nullptr, Z1h);
    hgemm<<<dim3(N_NODES / 128, 1), 256>>>(Z1h, W1h, N_NODES, W_OUT, W_OUT,
                                           b1, 2, Z2, nullptr);
    float* yout;
    bool with_loss;
    if (out_size >= M_TGT * NUM_CLASS + 1) { yout = (float*)d_out + 1; with_loss = true; }
    else if (out_size == M_TGT * NUM_CLASS) { yout = (float*)d_out; with_loss = false; }
    else { yout = ybuf; with_loss = true; }
    out_kernel<<<M_TGT, 128>>>(Z2, target_x, W2, b2, yout);
    if (with_loss) loss_kernel<<<1, 256>>>(yout, target, (float*)d_out);
}